// round 14
// baseline (speedup 1.0000x reference)
#include <cuda_runtime.h>
#include <cuda_fp16.h>
#include <cstdint>

#define NROWS   65536
#define IN_DIM  768
#define OUT_DIM 256
#define NLEV    4
#define KCODES  1024

// ---------------- device scratch ----------------
__device__ __align__(256) __half g_a0h[(size_t)NROWS * IN_DIM];   // xn hi; later d1 hi
__device__ __align__(256) __half g_a0m[(size_t)NROWS * IN_DIM];   // xn mid
__device__ __align__(256) __half g_h1h[(size_t)NROWS * OUT_DIM];  // h1 hi; later q hi
__device__ __align__(256) __half g_h1m[(size_t)NROWS * OUT_DIM];  // h1 mid; later q mid
__device__ __align__(256) __half g_resh[(size_t)NROWS * OUT_DIM]; // residual hi (authoritative)
__device__ __align__(256) __half g_resm[(size_t)NROWS * OUT_DIM]; // residual mid
__device__ __align__(256) float  g_qf [(size_t)NROWS * OUT_DIM];
__device__ __align__(256) __half g_wth[1048576];                  // transposed hi weights (packed)
__device__ __align__(256) __half g_wtm[1048576];                  // transposed mid weights
__device__ __align__(256) __half g_cbh[(size_t)NLEV * KCODES * OUT_DIM];
__device__ __align__(256) __half g_cbm[(size_t)NLEV * KCODES * OUT_DIM];
__device__ __align__(256) float  g_pb1[(size_t)8 * NROWS];  // per-block best score
__device__ __align__(256) int    g_pbI[(size_t)8 * NROWS];  // per-block best index
__device__ __align__(256) float  g_pb2[(size_t)8 * NROWS];  // per-block 2nd-best score
__device__ __align__(256) int    g_code[NROWS];
__device__ __align__(256) int    g_wl[NROWS];
__device__ int   g_cnt[8];
__device__ float g_cnorm[NLEV * KCODES];
__device__ float g_cmax[4 * NLEV];   // per level: max||ch||^2, max||cm||^2
__device__ float g_accum[8];

// ---------------- helpers ----------------
__device__ __forceinline__ uint32_t smem_u32(const void* p) {
    uint32_t a;
    asm("{ .reg .u64 t; cvta.to.shared.u64 t, %1; cvt.u32.u64 %0, t; }" : "=r"(a) : "l"(p));
    return a;
}
__device__ __forceinline__ void split2h(float v, __half& h, __half& m) {
    h = __float2half_rn(v);
    m = __float2half_rn(v - __half2float(h));
}
// merge top-2 triples: (v1,i1,v2) <- merge with (u1,j1,u2); index tie-break on i
__device__ __forceinline__ void merge2(float& v1, int& i1, float& v2,
                                       float u1, int j1, float u2) {
    if (u1 < v1 || (u1 == v1 && j1 < i1)) {
        v2 = fminf(v1, u2);
        v1 = u1; i1 = j1;
    } else {
        v2 = fminf(v2, u1);
    }
}

#define CP16(dst, src)  asm volatile("cp.async.cg.shared.global [%0], [%1], 16;" :: "r"(dst), "l"(src) : "memory")
#define CP_COMMIT()     asm volatile("cp.async.commit_group;" ::: "memory")
#define CP_WAIT1()      asm volatile("cp.async.wait_group 1;" ::: "memory")

#define LDMX4(r0, r1, r2, r3, addr) \
    asm volatile("ldmatrix.sync.aligned.m8n8.x4.shared.b16 {%0,%1,%2,%3}, [%4];" \
                 : "=r"(r0), "=r"(r1), "=r"(r2), "=r"(r3) : "r"(addr))

__device__ __forceinline__ void mma16816(float* c, const uint32_t* a, const uint32_t* b) {
    asm volatile(
        "mma.sync.aligned.m16n8k16.row.col.f32.f16.f16.f32 "
        "{%0,%1,%2,%3}, {%4,%5,%6,%7}, {%8,%9}, {%0,%1,%2,%3};"
        : "+f"(c[0]), "+f"(c[1]), "+f"(c[2]), "+f"(c[3])
        : "r"(a[0]), "r"(a[1]), "r"(a[2]), "r"(a[3]), "r"(b[0]), "r"(b[1]));
}

__device__ __forceinline__ float blockReduce256(float v, float* sbuf) {
    int tid = threadIdx.x;
#pragma unroll
    for (int o = 16; o > 0; o >>= 1) v += __shfl_down_sync(0xffffffffu, v, o);
    __syncthreads();
    if ((tid & 31) == 0) sbuf[tid >> 5] = v;
    __syncthreads();
    if (tid < 8) {
        v = sbuf[tid];
#pragma unroll
        for (int o = 4; o > 0; o >>= 1) v += __shfl_down_sync(0xffu, v, o);
    }
    return v;
}

// ---------------- small kernels ----------------
__global__ void zero_kernel(float* a, float* cm, int* cnt) {
    if (threadIdx.x < 8) { a[threadIdx.x] = 0.f; cnt[threadIdx.x] = 0; }
    if (threadIdx.x < 16) cm[threadIdx.x] = 0.f;
}

__global__ void ln_kernel(const float* __restrict__ x, const float* __restrict__ g,
                          const float* __restrict__ b,
                          __half* __restrict__ xh, __half* __restrict__ xm) {
    __shared__ float sbuf[8];
    __shared__ float mu_s, rstd_s;
    int row = blockIdx.x, tid = threadIdx.x;
    const float* xr = x + (size_t)row * IN_DIM;
    float v0 = xr[tid], v1 = xr[tid + 256], v2 = xr[tid + 512];
    float s = blockReduce256(v0 + v1 + v2, sbuf);
    if (tid == 0) mu_s = s * (1.f / IN_DIM);
    __syncthreads();
    float mu = mu_s;
    float d0 = v0 - mu, d1 = v1 - mu, d2 = v2 - mu;
    float q = blockReduce256(d0 * d0 + d1 * d1 + d2 * d2, sbuf);
    if (tid == 0) rstd_s = rsqrtf(q * (1.f / IN_DIM) + 1e-5f);
    __syncthreads();
    float rstd = rstd_s;
    size_t o = (size_t)row * IN_DIM;
    __half h, m;
    float y0 = d0 * rstd * g[tid]       + b[tid];
    float y1 = d1 * rstd * g[tid + 256] + b[tid + 256];
    float y2 = d2 * rstd * g[tid + 512] + b[tid + 512];
    split2h(y0, h, m); xh[o + tid]       = h; xm[o + tid]       = m;
    split2h(y1, h, m); xh[o + tid + 256] = h; xm[o + tid + 256] = m;
    split2h(y2, h, m); xh[o + tid + 512] = h; xm[o + tid + 512] = m;
}

// transpose + split: W [K,N] row-major -> Bh/Bm [N,K] half
__global__ void wsplit_kernel(const float* __restrict__ W, __half* __restrict__ Bh,
                              __half* __restrict__ Bm, int K, int N) {
    int i = blockIdx.x * 256 + threadIdx.x;
    if (i >= K * N) return;
    int k = i / N, n = i % N;
    __half h, m;
    split2h(W[i], h, m);
    Bh[(size_t)n * K + k] = h;
    Bm[(size_t)n * K + k] = m;
}

__global__ void cbsplit_kernel(const float* __restrict__ cb, __half* __restrict__ h,
                               __half* __restrict__ m) {
    size_t i = (size_t)blockIdx.x * 256 + threadIdx.x;
    __half hh, mm;
    split2h(cb[i], hh, mm);
    h[i] = hh; m[i] = mm;
}

// per-code norms + per-level max split-norms (for rigorous argmin margin)
__global__ void cnorm_kernel(const float* __restrict__ cb, float* __restrict__ cn,
                             float* __restrict__ cmax) {
    int gw = (blockIdx.x * blockDim.x + threadIdx.x) >> 5;
    int lane = threadIdx.x & 31;
    if (gw >= NLEV * KCODES) return;
    const float4* c = (const float4*)(cb + (size_t)gw * OUT_DIM);
    float s = 0.f, sh = 0.f, sm = 0.f;
#pragma unroll
    for (int i = 0; i < 2; i++) {
        float4 v = c[lane + i * 32];
        s += v.x * v.x + v.y * v.y + v.z * v.z + v.w * v.w;
        __half hh, mm;
        float hf, mf;
        split2h(v.x, hh, mm); hf = __half2float(hh); mf = __half2float(mm); sh += hf*hf; sm += mf*mf;
        split2h(v.y, hh, mm); hf = __half2float(hh); mf = __half2float(mm); sh += hf*hf; sm += mf*mf;
        split2h(v.z, hh, mm); hf = __half2float(hh); mf = __half2float(mm); sh += hf*hf; sm += mf*mf;
        split2h(v.w, hh, mm); hf = __half2float(hh); mf = __half2float(mm); sh += hf*hf; sm += mf*mf;
    }
#pragma unroll
    for (int o = 16; o > 0; o >>= 1) {
        s  += __shfl_down_sync(0xffffffffu, s, o);
        sh += __shfl_down_sync(0xffffffffu, sh, o);
        sm += __shfl_down_sync(0xffffffffu, sm, o);
    }
    if (lane == 0) {
        cn[gw] = s;
        int lvl = gw >> 10;
        atomicMax((int*)&cmax[lvl * 4],     __float_as_int(sh));
        atomicMax((int*)&cmax[lvl * 4 + 1], __float_as_int(sm));
    }
}

// merge 8 per-block top-2 partials; certify gap vs rigorous bound E.
// Certified -> code; else append row to worklist. One warp per row.
__global__ __launch_bounds__(256)
void combine2_kernel(const float* __restrict__ pb1, const int* __restrict__ pbI,
                     const float* __restrict__ pb2,
                     const __half* __restrict__ resh, const __half* __restrict__ resm,
                     const float* __restrict__ cmax,
                     int* __restrict__ code, int* __restrict__ wl, int* __restrict__ cnt) {
    int wid = threadIdx.x >> 5, lane = threadIdx.x & 31;
    int row = blockIdx.x * 8 + wid;

    float v1 = 3.4e38f, v2 = 3.4e38f;
    int i1 = 0x7fffffff;
    if (lane < 8) {
        v1 = pb1[(size_t)lane * NROWS + row];
        i1 = pbI[(size_t)lane * NROWS + row];
        v2 = pb2[(size_t)lane * NROWS + row];
    }
#pragma unroll
    for (int o = 1; o <= 4; o <<= 1) {
        float u1 = __shfl_xor_sync(0xffffffffu, v1, o);
        int j1 = __shfl_xor_sync(0xffffffffu, i1, o);
        float u2 = __shfl_xor_sync(0xffffffffu, v2, o);
        merge2(v1, i1, v2, u1, j1, u2);
    }
    v1 = __shfl_sync(0xffffffffu, v1, 0);
    i1 = __shfl_sync(0xffffffffu, i1, 0);
    v2 = __shfl_sync(0xffffffffu, v2, 0);

    // row split norms
    size_t ro = (size_t)row * OUT_DIM;
    float h2 = 0.f, m2 = 0.f;
#pragma unroll
    for (int k = 0; k < 8; k++) {
        float hv = __half2float(resh[ro + lane * 8 + k]);
        float mv = __half2float(resm[ro + lane * 8 + k]);
        h2 += hv * hv; m2 += mv * mv;
    }
#pragma unroll
    for (int o = 16; o > 0; o >>= 1) {
        h2 += __shfl_xor_sync(0xffffffffu, h2, o);
        m2 += __shfl_xor_sync(0xffffffffu, m2, o);
    }
    if (lane == 0) {
        float nrh = sqrtf(h2), nrm = sqrtf(m2);
        float maxCh = sqrtf(cmax[0]), maxCm = sqrtf(cmax[1]);
        float E = 2.f * (nrh * maxCm + nrm * (maxCh + maxCm))
                + 5e-5f * nrh * maxCh + 1e-2f;
        if (v2 - v1 > 2.f * E) {
            code[row] = i1;
        } else {
            int pos = atomicAdd(cnt, 1);
            wl[pos] = row;
        }
    }
}

// exact fp32 scan over all 1024 codes for uncertified rows. One warp per entry.
__global__ __launch_bounds__(256)
void cleanup_kernel(const int* __restrict__ wl, const int* __restrict__ cnt,
                    const __half* __restrict__ resh, const __half* __restrict__ resm,
                    const float* __restrict__ cb, const float* __restrict__ cn,
                    int* __restrict__ code) {
    int lane = threadIdx.x & 31;
    int warp = (blockIdx.x * 256 + threadIdx.x) >> 5;
    int nwarp = gridDim.x * 8;
    int n = cnt[0];
    for (int e = warp; e < n; e += nwarp) {
        int row = wl[e];
        size_t ro = (size_t)row * OUT_DIM;
        float rr[8];
#pragma unroll
        for (int k = 0; k < 8; k++)
            rr[k] = __half2float(resh[ro + lane * 8 + k]) + __half2float(resm[ro + lane * 8 + k]);
        float bestS = 3.4e38f;
        int bestI = 0;
        for (int j = 0; j < KCODES; j++) {
            const float4* cr = (const float4*)(cb + (size_t)j * OUT_DIM);
            float4 x1 = cr[lane * 2], x2 = cr[lane * 2 + 1];
            float acc = rr[0] * x1.x + rr[1] * x1.y + rr[2] * x1.z + rr[3] * x1.w
                      + rr[4] * x2.x + rr[5] * x2.y + rr[6] * x2.z + rr[7] * x2.w;
#pragma unroll
            for (int o = 16; o > 0; o >>= 1) acc += __shfl_xor_sync(0xffffffffu, acc, o);
            float se = cn[j] - 2.f * acc;
            if (se < bestS) { bestS = se; bestI = j; }
        }
        if (lane == 0) code[row] = bestI;
    }
}

// residual update: reconstruct r from hi/mid splits, d = r - cb[code], re-split.
// mode 0=first level, 1=middle, 2=last (writes q splits to qh/qm instead)
__global__ void update_kernel(const float* __restrict__ cb, const int* __restrict__ code,
                              __half* __restrict__ resh, __half* __restrict__ resm,
                              float* __restrict__ qf,
                              __half* __restrict__ qh, __half* __restrict__ qm,
                              int mode, float* __restrict__ commit,
                              float* __restrict__ idxf, int lvl) {
    __shared__ float sbuf[8];
    int tt = blockIdx.x * 256 + threadIdx.x;
    int row = tt >> 6, lane = tt & 63;
    int cd = code[row];
    size_t ro = (size_t)row * OUT_DIM + lane * 4;
    float4 c = *(const float4*)(cb + (size_t)cd * OUT_DIM + lane * 4);
    __half2 rh01 = *(const __half2*)(resh + ro), rh23 = *(const __half2*)(resh + ro + 2);
    __half2 rm01 = *(const __half2*)(resm + ro), rm23 = *(const __half2*)(resm + ro + 2);
    float4 r;
    r.x = __half2float(__low2half(rh01))  + __half2float(__low2half(rm01));
    r.y = __half2float(__high2half(rh01)) + __half2float(__high2half(rm01));
    r.z = __half2float(__low2half(rh23))  + __half2float(__low2half(rm23));
    r.w = __half2float(__high2half(rh23)) + __half2float(__high2half(rm23));
    float4 d;
    d.x = r.x - c.x; d.y = r.y - c.y; d.z = r.z - c.z; d.w = r.w - c.w;
    if (mode != 2) {
        __half h0, m0, h1, m1, h2, m2, h3, m3;
        split2h(d.x, h0, m0); split2h(d.y, h1, m1);
        split2h(d.z, h2, m2); split2h(d.w, h3, m3);
        *(__half2*)(resh + ro)     = __halves2half2(h0, h1);
        *(__half2*)(resh + ro + 2) = __halves2half2(h2, h3);
        *(__half2*)(resm + ro)     = __halves2half2(m0, m1);
        *(__half2*)(resm + ro + 2) = __halves2half2(m2, m3);
    }
    float4 qn;
    if (mode == 0) {
        qn = c;
    } else {
        float4 qo = *(const float4*)(qf + ro);
        qn.x = qo.x + c.x; qn.y = qo.y + c.y; qn.z = qo.z + c.z; qn.w = qo.w + c.w;
    }
    if (mode != 2) {
        *(float4*)(qf + ro) = qn;
    } else {
        __half h0, m0, h1, m1, h2, m2, h3, m3;
        split2h(qn.x, h0, m0); split2h(qn.y, h1, m1);
        split2h(qn.z, h2, m2); split2h(qn.w, h3, m3);
        *(__half2*)(qh + ro)     = __halves2half2(h0, h1);
        *(__half2*)(qh + ro + 2) = __halves2half2(h2, h3);
        *(__half2*)(qm + ro)     = __halves2half2(m0, m1);
        *(__half2*)(qm + ro + 2) = __halves2half2(m2, m3);
    }
    if (lane == 0 && idxf) idxf[(size_t)row * 4 + lvl] = (float)cd;
    float s = d.x * d.x + d.y * d.y + d.z * d.z + d.w * d.w;
    s = blockReduce256(s, sbuf);
    if (threadIdx.x == 0) atomicAdd(commit, s);
}

__global__ void finalize_kernel(const float* __restrict__ a, float* __restrict__ out) {
    out[0] = a[0] * (1.f / ((float)NROWS * IN_DIM))
           + 0.25f * a[1] * (1.f / ((float)NROWS * OUT_DIM));
}

// ---------------- fp16-split GEMM on mma.sync (HMMA) ----------------
// Block tile M=128 x N=128, 256 threads (8 warps), warp tile 32x64, K-step 16,
// 3-stage cp.async pipeline, 2 CTAs/SM.
// Stage layout (24576B): Ah[128r x 48B]=6144 | Am=6144 | Bh[128r x 48B]=6144 | Bm=6144
// NT=3: D = Ah*Bh + Ah*Bm + Am*Bh.  NT=2: D = Ah*Bh + Ah*Bm.  NT=1: D = Ah*Bh.
// MODE 0: relu(D+bias) -> Oh (and Om if non-null)
// MODE 1: c=D+bias -> Oh, Om (hi/mid split only)
// MODE 2: c=D+bias -> Of, partial += (c-aux)^2 -> accum
// MODE 3: per-row top-2 of (aux[col]-2D) over this block's 128 codes -> Of (best),
//         iOut (best idx), Of2 (2nd best), at [blockIdx.x*NROWS + bm + tid]
#define STAGE_B 24576
#define SMEM_MMA (3 * STAGE_B)

template <int MODE, int NT>
__global__ __launch_bounds__(256, 2)
void mma_gemm(int K, int Nout, int nct,
              const __half* __restrict__ Ah, const __half* __restrict__ Am,
              const __half* __restrict__ Bh, const __half* __restrict__ Bm,
              const float* __restrict__ bias,
              float* __restrict__ Of, __half* __restrict__ Oh, __half* __restrict__ Om,
              const float* __restrict__ aux, float* __restrict__ accum,
              float* __restrict__ Of2, int* __restrict__ iOut) {
    extern __shared__ char dsm[];
    __shared__ float sred[8];
    uint32_t smb = smem_u32(dsm);
    int tid = threadIdx.x, lane = tid & 31, wid = tid >> 5;
    int bm = blockIdx.y * 128;
    int bn0 = blockIdx.x * 128 * nct;
    int wm = (wid & 3) * 32, wn = (wid >> 2) * 64;

    const __half* Abh = Ah + (size_t)bm * K;
    const __half* Abm = Am + (size_t)bm * K;

    int crow = tid >> 1, csub = tid & 1;
    uint32_t cdst = (uint32_t)(crow * 48 + csub * 16);
    size_t csrc = (size_t)crow * K + csub * 8;

    uint32_t aoffA = (uint32_t)((wm + (lane & 15)) * 48 + ((lane >> 4) & 1) * 16);
    uint32_t aoffB = (uint32_t)(12288 + (wn + (lane & 7) + ((lane >> 4) & 1) * 8) * 48
                                + ((lane >> 3) & 1) * 16);

    float bV1[4], bV2[4];
    int bI1[4];
#pragma unroll
    for (int i = 0; i < 4; i++) { bV1[i] = 3.4e38f; bV2[i] = 3.4e38f; bI1[i] = 0x7fffffff; }
    float partial = 0.f;
    int nk = K >> 4;

    for (int ct = 0; ct < nct; ct++) {
        const __half* Bth = Bh + (size_t)(bn0 + ct * 128) * K;
        const __half* Btm = Bm + (size_t)(bn0 + ct * 128) * K;
        float c[2][8][4];
#pragma unroll
        for (int mt = 0; mt < 2; mt++)
#pragma unroll
            for (int nt = 0; nt < 8; nt++)
#pragma unroll
                for (int k = 0; k < 4; k++) c[mt][nt][k] = 0.f;

        __syncthreads();
#pragma unroll
        for (int s = 0; s < 2; s++) {
            uint32_t sb = smb + s * STAGE_B;
            int ko = s * 16;
            CP16(sb + cdst, (const void*)(Abh + csrc + ko));
            if (NT == 3) CP16(sb + 6144 + cdst, (const void*)(Abm + csrc + ko));
            CP16(sb + 12288 + cdst, (const void*)(Bth + csrc + ko));
            if (NT >= 2) CP16(sb + 18432 + cdst, (const void*)(Btm + csrc + ko));
            CP_COMMIT();
        }

        for (int kt = 0; kt < nk; kt++) {
            int s = kt % 3;
            CP_WAIT1();
            __syncthreads();
            if (kt + 2 < nk) {
                uint32_t sb = smb + ((kt + 2) % 3) * STAGE_B;
                int ko = (kt + 2) * 16;
                CP16(sb + cdst, (const void*)(Abh + csrc + ko));
                if (NT == 3) CP16(sb + 6144 + cdst, (const void*)(Abm + csrc + ko));
                CP16(sb + 12288 + cdst, (const void*)(Bth + csrc + ko));
                if (NT >= 2) CP16(sb + 18432 + cdst, (const void*)(Btm + csrc + ko));
            }
            CP_COMMIT();

            uint32_t sb = smb + s * STAGE_B;
            uint32_t ah[2][4], am[2][4];
#pragma unroll
            for (int mt = 0; mt < 2; mt++) {
                uint32_t ad = sb + aoffA + mt * 768;
                LDMX4(ah[mt][0], ah[mt][1], ah[mt][2], ah[mt][3], ad);
                if (NT == 3)
                    LDMX4(am[mt][0], am[mt][1], am[mt][2], am[mt][3], ad + 6144);
            }
#pragma unroll
            for (int p = 0; p < 4; p++) {
                uint32_t bh[4], bmf[4];
                uint32_t bd = sb + aoffB + p * 768;
                LDMX4(bh[0], bh[1], bh[2], bh[3], bd);
                if (NT >= 2)
                    LDMX4(bmf[0], bmf[1], bmf[2], bmf[3], bd + 6144);
#pragma unroll
                for (int mt = 0; mt < 2; mt++)
#pragma unroll
                    for (int q = 0; q < 2; q++) {
                        int nt = 2 * p + q;
                        mma16816(c[mt][nt], ah[mt], &bh[2 * q]);
                        if (NT >= 2) mma16816(c[mt][nt], ah[mt], &bmf[2 * q]);
                        if (NT == 3) mma16816(c[mt][nt], am[mt], &bh[2 * q]);
                    }
            }
        }

        // ---------------- epilogue ----------------
        if (MODE == 3) {
#pragma unroll
            for (int mt = 0; mt < 2; mt++)
#pragma unroll
                for (int h = 0; h < 2; h++) {
                    int slot = mt * 2 + h;
#pragma unroll
                    for (int nt = 0; nt < 8; nt++) {
                        int col = bn0 + ct * 128 + wn + nt * 8 + (lane & 3) * 2;
#pragma unroll
                        for (int j = 0; j < 2; j++) {
                            float v = aux[col + j] - 2.f * c[mt][nt][h * 2 + j];
                            if (v < bV1[slot]) {
                                bV2[slot] = bV1[slot];
                                bV1[slot] = v; bI1[slot] = col + j;
                            } else if (v < bV2[slot]) {
                                bV2[slot] = v;
                            }
                        }
                    }
                }
        } else {
#pragma unroll
            for (int mt = 0; mt < 2; mt++)
#pragma unroll
                for (int h = 0; h < 2; h++) {
                    int row = bm + wm + mt * 16 + (lane >> 2) + h * 8;
#pragma unroll
                    for (int nt = 0; nt < 8; nt++) {
                        int col = bn0 + ct * 128 + wn + nt * 8 + (lane & 3) * 2;
                        float v0 = c[mt][nt][h * 2 + 0] + bias[col];
                        float v1 = c[mt][nt][h * 2 + 1] + bias[col + 1];
                        size_t o = (size_t)row * Nout + col;
                        if (MODE == 0) {
                            v0 = fmaxf(v0, 0.f); v1 = fmaxf(v1, 0.f);
                            __half h0, m0, h1x, m1x;
                            split2h(v0, h0, m0); split2h(v1, h1x, m1x);
                            *(__half2*)(Oh + o) = __halves2half2(h0, h1x);
                            if (Om) *(__half2*)(Om + o) = __halves2half2(m0, m1x);
                        } else if (MODE == 1) {
                            __half h0, m0, h1x, m1x;
                            split2h(v0, h0, m0); split2h(v1, h1x, m1x);
                            *(__half2*)(Oh + o) = __halves2half2(h0, h1x);
                            *(__half2*)(Om + o) = __halves2half2(m0, m1x);
                        } else {  // MODE 2
                            Of[o] = v0; Of[o + 1] = v1;
                            float e0 = v0 - aux[o], e1 = v1 - aux[o + 1];
                            partial += e0 * e0 + e1 * e1;
                        }
                    }
                }
        }
    }

    if (MODE == 3) {
        // quad merge (cols within quad)
#pragma unroll
        for (int slot = 0; slot < 4; slot++) {
#pragma unroll
            for (int o = 1; o <= 2; o <<= 1) {
                float u1 = __shfl_xor_sync(0xffffffffu, bV1[slot], o);
                int j1 = __shfl_xor_sync(0xffffffffu, bI1[slot], o);
                float u2 = __shfl_xor_sync(0xffffffffu, bV2[slot], o);
                merge2(bV1[slot], bI1[slot], bV2[slot], u1, j1, u2);
            }
        }
        float* sV1 = (float*)dsm;           // [128][2]
        int* sI1 = (int*)(dsm + 1024);      // [128][2]
        float* sV2 = (float*)(dsm + 2048);  // [128][2]
        __syncthreads();
        if ((lane & 3) == 0) {
            int g = wid >> 2;
#pragma unroll
            for (int mt = 0; mt < 2; mt++)
#pragma unroll
                for (int h = 0; h < 2; h++) {
                    int lr = wm + mt * 16 + (lane >> 2) + h * 8;
                    int slot = mt * 2 + h;
                    sV1[lr * 2 + g] = bV1[slot];
                    sI1[lr * 2 + g] = bI1[slot];
                    sV2[lr * 2 + g] = bV2[slot];
                }
        }
        __syncthreads();
        if (tid < 128) {
            float v1 = sV1[tid * 2], v2 = sV2[tid * 2];
            int i1 = sI1[tid * 2];
            merge2(v1, i1, v2, sV1[tid * 2 + 1], sI1[tid * 2 + 1], sV2[tid * 2 + 1]);
            size_t po = (size_t)blockIdx.x * NROWS + bm + tid;
            Of[po] = v1;
            iOut[po] = i1;
            Of2[po] = v2;
        }
    }
    if (MODE == 2) {
        partial = blockReduce256(partial, sred);
        if (tid == 0) atomicAdd(accum, partial);
    }
}

// ---------------- launch ----------------
extern "C" void kernel_launch(void* const* d_in, const int* in_sizes, int n_in,
                              void* d_out, int out_size) {
    const float* x    = (const float*)d_in[0];
    const float* ln_g = (const float*)d_in[1];
    const float* ln_b = (const float*)d_in[2];
    const float* W1   = (const float*)d_in[3];
    const float* b1   = (const float*)d_in[4];
    const float* W2   = (const float*)d_in[5];
    const float* b2   = (const float*)d_in[6];
    const float* Wd1  = (const float*)d_in[7];
    const float* bd1  = (const float*)d_in[8];
    const float* Wd2  = (const float*)d_in[9];
    const float* bd2  = (const float*)d_in[10];
    const float* cbs  = (const float*)d_in[11];
    float* out = (float*)d_out;

    __half *a0h, *a0m, *h1h, *h1m, *resh, *resm, *wth, *wtm, *cbh, *cbm;
    float *qf, *cnorm, *accum, *cmax, *pb1, *pb2;
    int *pbI, *codep, *wl, *cnt;
    cudaGetSymbolAddress((void**)&a0h,  g_a0h);
    cudaGetSymbolAddress((void**)&a0m,  g_a0m);
    cudaGetSymbolAddress((void**)&h1h,  g_h1h);
    cudaGetSymbolAddress((void**)&h1m,  g_h1m);
    cudaGetSymbolAddress((void**)&resh, g_resh);
    cudaGetSymbolAddress((void**)&resm, g_resm);
    cudaGetSymbolAddress((void**)&qf,   g_qf);
    cudaGetSymbolAddress((void**)&wth,  g_wth);
    cudaGetSymbolAddress((void**)&wtm,  g_wtm);
    cudaGetSymbolAddress((void**)&cbh,  g_cbh);
    cudaGetSymbolAddress((void**)&cbm,  g_cbm);
    cudaGetSymbolAddress((void**)&pb1,  g_pb1);
    cudaGetSymbolAddress((void**)&pb2,  g_pb2);
    cudaGetSymbolAddress((void**)&pbI,  g_pbI);
    cudaGetSymbolAddress((void**)&codep, g_code);
    cudaGetSymbolAddress((void**)&wl,   g_wl);
    cudaGetSymbolAddress((void**)&cnt,  g_cnt);
    cudaGetSymbolAddress((void**)&cnorm, g_cnorm);
    cudaGetSymbolAddress((void**)&cmax, g_cmax);
    cudaGetSymbolAddress((void**)&accum, g_accum);

    cudaFuncSetAttribute(mma_gemm<0, 3>, cudaFuncAttributeMaxDynamicSharedMemorySize, SMEM_MMA);
    cudaFuncSetAttribute(mma_gemm<1, 3>, cudaFuncAttributeMaxDynamicSharedMemorySize, SMEM_MMA);
    cudaFuncSetAttribute(mma_gemm<2, 2>, cudaFuncAttributeMaxDynamicSharedMemorySize, SMEM_MMA);
    cudaFuncSetAttribute(mma_gemm<3, 1>, cudaFuncAttributeMaxDynamicSharedMemorySize, SMEM_MMA);

    const size_t reconElems = (size_t)NROWS * IN_DIM;
    size_t reconOff = ((size_t)out_size == reconElems) ? 0 : 1;
    bool fullOut = ((size_t)out_size >= 1 + reconElems + (size_t)NROWS * 4);
    float* idxf = fullOut ? (out + 1 + reconElems) : nullptr;

    // Launch order: enc1 is launch #4 here = ncu's captured launch (offset +2).
    ln_kernel<<<NROWS, 256>>>(x, ln_g, ln_b, a0h, a0m);                        // 1
    wsplit_kernel<<<(768 * 256 + 255) / 256, 256>>>(W1, wth, wtm, 768, 256);   // 2
    zero_kernel<<<1, 32>>>(accum, cmax, cnt);                                  // 3
    // 4: encoder GEMM1 (target of ncu capture)
    mma_gemm<0, 3><<<dim3(2, 512), 256, SMEM_MMA>>>(768, 256, 1, a0h, a0m, wth, wtm, b1,
                                                    nullptr, h1h, h1m, nullptr, nullptr,
                                                    nullptr, nullptr);
    wsplit_kernel<<<(256 * 256 + 255) / 256, 256>>>(W2, wth + 196608, wtm + 196608, 256, 256);
    mma_gemm<1, 3><<<dim3(2, 512), 256, SMEM_MMA>>>(256, 256, 1, h1h, h1m,
                                                    wth + 196608, wtm + 196608, b2,
                                                    nullptr, resh, resm, nullptr, nullptr,
                                                    nullptr, nullptr);
    cbsplit_kernel<<<(NLEV * KCODES * OUT_DIM) / 256, 256>>>(cbs, cbh, cbm);
    cnorm_kernel<<<(NLEV * KCODES * 32) / 256, 256>>>(cbs, cnorm, cmax);

    // residual quantization: 1-term top-2 partials -> certify -> cleanup -> update
    for (int l = 0; l < NLEV; l++) {
        const __half* cbhl = cbh + (size_t)l * KCODES * OUT_DIM;
        const float* cbl = cbs + (size_t)l * KCODES * OUT_DIM;
        mma_gemm<3, 1><<<dim3(8, 512), 256, SMEM_MMA>>>(256, 0, 1, resh, resh,
                                                        cbhl, cbhl, nullptr,
                                                        pb1, nullptr, nullptr,
                                                        cnorm + l * KCODES, nullptr,
                                                        pb2, pbI);
        combine2_kernel<<<NROWS / 8, 256>>>(pb1, pbI, pb2, resh, resm,
                                            cmax + 4 * l, codep, wl, cnt + l);
        cleanup_kernel<<<512, 256>>>(wl, cnt + l, resh, resm, cbl,
                                     cnorm + l * KCODES, codep);
        int mode = (l == 0) ? 0 : ((l == NLEV - 1) ? 2 : 1);
        update_kernel<<<(NROWS * 64) / 256, 256>>>(cbl, codep, resh, resm, qf, h1h, h1m,
                                                   mode, accum + 1, idxf, l);
    }

    // decoder: dec1 3-term (d1-mid not stored), dec2 2-term
    wsplit_kernel<<<(256 * 768 + 255) / 256, 256>>>(Wd1, wth + 262144, wtm + 262144, 256, 768);
    mma_gemm<0, 3><<<dim3(6, 512), 256, SMEM_MMA>>>(256, 768, 1, h1h, h1m,
                                                    wth + 262144, wtm + 262144, bd1,
                                                    nullptr, a0h, nullptr, nullptr, nullptr,
                                                    nullptr, nullptr);
    wsplit_kernel<<<(768 * 768 + 255) / 256, 256>>>(Wd2, wth + 458752, wtm + 458752, 768, 768);
    mma_gemm<2, 2><<<dim3(6, 512), 256, SMEM_MMA>>>(768, 768, 1, a0h, a0h,
                                                    wth + 458752, wtm + 458752, bd2,
                                                    out + reconOff, nullptr, nullptr, x, accum,
                                                    nullptr, nullptr);

    if (fullOut) {
        finalize_kernel<<<1, 1>>>(accum, out);
    }
}

// round 15
// speedup vs baseline: 1.3864x; 1.3864x over previous
#include <cuda_runtime.h>
#include <cuda_fp16.h>
#include <cstdint>

#define NROWS   65536
#define IN_DIM  768
#define OUT_DIM 256
#define NLEV    4
#define KCODES  1024

// ---------------- device scratch ----------------
__device__ __align__(256) __half g_a0h[(size_t)NROWS * IN_DIM];   // xn hi; later d1 hi
__device__ __align__(256) __half g_a0m[(size_t)NROWS * IN_DIM];   // xn mid
__device__ __align__(256) __half g_h1h[(size_t)NROWS * OUT_DIM];  // h1 hi; later q hi
__device__ __align__(256) __half g_h1m[(size_t)NROWS * OUT_DIM];  // h1 mid; later q mid
__device__ __align__(256) __half g_resh[(size_t)NROWS * OUT_DIM]; // residual hi (authoritative)
__device__ __align__(256) __half g_resm[(size_t)NROWS * OUT_DIM]; // residual mid
__device__ __align__(256) float  g_qf [(size_t)NROWS * OUT_DIM];
__device__ __align__(256) __half g_wth[1048576];                  // transposed hi weights (packed)
__device__ __align__(256) __half g_wtm[1048576];                  // transposed mid weights
__device__ __align__(256) __half g_cbh[(size_t)NLEV * KCODES * OUT_DIM];
__device__ __align__(256) __half g_cbm[(size_t)NLEV * KCODES * OUT_DIM];
__device__ __align__(256) float  g_pbV[(size_t)8 * NROWS];        // per-tile argmin partials
__device__ __align__(256) int    g_pbI[(size_t)8 * NROWS];
__device__ float g_cnorm[NLEV * KCODES];
__device__ float g_accum[8];

// ---------------- helpers ----------------
__device__ __forceinline__ uint32_t smem_u32(const void* p) {
    uint32_t a;
    asm("{ .reg .u64 t; cvta.to.shared.u64 t, %1; cvt.u32.u64 %0, t; }" : "=r"(a) : "l"(p));
    return a;
}
__device__ __forceinline__ void split2h(float v, __half& h, __half& m) {
    h = __float2half_rn(v);
    m = __float2half_rn(v - __half2float(h));
}

#define CP16(dst, src)  asm volatile("cp.async.cg.shared.global [%0], [%1], 16;" :: "r"(dst), "l"(src) : "memory")
#define CP_COMMIT()     asm volatile("cp.async.commit_group;" ::: "memory")
#define CP_WAIT1()      asm volatile("cp.async.wait_group 1;" ::: "memory")

#define LDMX4(r0, r1, r2, r3, addr) \
    asm volatile("ldmatrix.sync.aligned.m8n8.x4.shared.b16 {%0,%1,%2,%3}, [%4];" \
                 : "=r"(r0), "=r"(r1), "=r"(r2), "=r"(r3) : "r"(addr))

__device__ __forceinline__ void mma16816(float* c, const uint32_t* a, const uint32_t* b) {
    asm volatile(
        "mma.sync.aligned.m16n8k16.row.col.f32.f16.f16.f32 "
        "{%0,%1,%2,%3}, {%4,%5,%6,%7}, {%8,%9}, {%0,%1,%2,%3};"
        : "+f"(c[0]), "+f"(c[1]), "+f"(c[2]), "+f"(c[3])
        : "r"(a[0]), "r"(a[1]), "r"(a[2]), "r"(a[3]), "r"(b[0]), "r"(b[1]));
}

__device__ __forceinline__ float blockReduce256(float v, float* sbuf) {
    int tid = threadIdx.x;
#pragma unroll
    for (int o = 16; o > 0; o >>= 1) v += __shfl_down_sync(0xffffffffu, v, o);
    __syncthreads();
    if ((tid & 31) == 0) sbuf[tid >> 5] = v;
    __syncthreads();
    if (tid < 8) {
        v = sbuf[tid];
#pragma unroll
        for (int o = 4; o > 0; o >>= 1) v += __shfl_down_sync(0xffu, v, o);
    }
    return v;
}

// ---------------- small kernels ----------------
__global__ void zero_kernel(float* a) {
    if (threadIdx.x < 8) a[threadIdx.x] = 0.f;
}

__global__ void ln_kernel(const float* __restrict__ x, const float* __restrict__ g,
                          const float* __restrict__ b,
                          __half* __restrict__ xh, __half* __restrict__ xm) {
    __shared__ float sbuf[8];
    __shared__ float mu_s, rstd_s;
    int row = blockIdx.x, tid = threadIdx.x;
    const float* xr = x + (size_t)row * IN_DIM;
    float v0 = xr[tid], v1 = xr[tid + 256], v2 = xr[tid + 512];
    float s = blockReduce256(v0 + v1 + v2, sbuf);
    if (tid == 0) mu_s = s * (1.f / IN_DIM);
    __syncthreads();
    float mu = mu_s;
    float d0 = v0 - mu, d1 = v1 - mu, d2 = v2 - mu;
    float q = blockReduce256(d0 * d0 + d1 * d1 + d2 * d2, sbuf);
    if (tid == 0) rstd_s = rsqrtf(q * (1.f / IN_DIM) + 1e-5f);
    __syncthreads();
    float rstd = rstd_s;
    size_t o = (size_t)row * IN_DIM;
    __half h, m;
    float y0 = d0 * rstd * g[tid]       + b[tid];
    float y1 = d1 * rstd * g[tid + 256] + b[tid + 256];
    float y2 = d2 * rstd * g[tid + 512] + b[tid + 512];
    split2h(y0, h, m); xh[o + tid]       = h; xm[o + tid]       = m;
    split2h(y1, h, m); xh[o + tid + 256] = h; xm[o + tid + 256] = m;
    split2h(y2, h, m); xh[o + tid + 512] = h; xm[o + tid + 512] = m;
}

// transpose + split: W [K,N] row-major -> Bh/Bm [N,K] half
__global__ void wsplit_kernel(const float* __restrict__ W, __half* __restrict__ Bh,
                              __half* __restrict__ Bm, int K, int N) {
    int i = blockIdx.x * 256 + threadIdx.x;
    if (i >= K * N) return;
    int k = i / N, n = i % N;
    __half h, m;
    split2h(W[i], h, m);
    Bh[(size_t)n * K + k] = h;
    Bm[(size_t)n * K + k] = m;
}

__global__ void cbsplit_kernel(const float* __restrict__ cb, __half* __restrict__ h,
                               __half* __restrict__ m) {
    size_t i = (size_t)blockIdx.x * 256 + threadIdx.x;
    __half hh, mm;
    split2h(cb[i], hh, mm);
    h[i] = hh; m[i] = mm;
}

__global__ void cnorm_kernel(const float* __restrict__ cb, float* __restrict__ cn) {
    int gw = (blockIdx.x * blockDim.x + threadIdx.x) >> 5;
    int lane = threadIdx.x & 31;
    if (gw >= NLEV * KCODES) return;
    const float4* c = (const float4*)(cb + (size_t)gw * OUT_DIM);
    float s = 0.f;
#pragma unroll
    for (int i = 0; i < 2; i++) {
        float4 v = c[lane + i * 32];
        s += v.x * v.x + v.y * v.y + v.z * v.z + v.w * v.w;
    }
#pragma unroll
    for (int o = 16; o > 0; o >>= 1) s += __shfl_down_sync(0xffffffffu, s, o);
    if (lane == 0) cn[gw] = s;
}

// fused combine + residual update:
// merge 8 per-tile argmin partials (ascending tile order, first-index tie-break),
// then d = r - cb[code], re-split; q accumulate; commit loss; idx output.
// mode 0=first level, 1=middle, 2=last (writes q splits to qh/qm instead)
__global__ void update_kernel(const float* __restrict__ cb,
                              const float* __restrict__ pbV, const int* __restrict__ pbI,
                              __half* __restrict__ resh, __half* __restrict__ resm,
                              float* __restrict__ qf,
                              __half* __restrict__ qh, __half* __restrict__ qm,
                              int mode, float* __restrict__ commit,
                              float* __restrict__ idxf, int lvl) {
    __shared__ float sbuf[8];
    int tt = blockIdx.x * 256 + threadIdx.x;
    int row = tt >> 6, lane = tt & 63;
    // inline 8-way partial merge (same order/comparison as R11's combine_kernel)
    float bv = pbV[row];
    int bi = pbI[row];
#pragma unroll
    for (int j = 1; j < 8; j++) {
        float v = pbV[(size_t)j * NROWS + row];
        int ii = pbI[(size_t)j * NROWS + row];
        if (v < bv || (v == bv && ii < bi)) { bv = v; bi = ii; }
    }
    int cd = bi;
    size_t ro = (size_t)row * OUT_DIM + lane * 4;
    float4 c = *(const float4*)(cb + (size_t)cd * OUT_DIM + lane * 4);
    __half2 rh01 = *(const __half2*)(resh + ro), rh23 = *(const __half2*)(resh + ro + 2);
    __half2 rm01 = *(const __half2*)(resm + ro), rm23 = *(const __half2*)(resm + ro + 2);
    float4 r;
    r.x = __half2float(__low2half(rh01))  + __half2float(__low2half(rm01));
    r.y = __half2float(__high2half(rh01)) + __half2float(__high2half(rm01));
    r.z = __half2float(__low2half(rh23))  + __half2float(__low2half(rm23));
    r.w = __half2float(__high2half(rh23)) + __half2float(__high2half(rm23));
    float4 d;
    d.x = r.x - c.x; d.y = r.y - c.y; d.z = r.z - c.z; d.w = r.w - c.w;
    if (mode != 2) {
        __half h0, m0, h1, m1, h2, m2, h3, m3;
        split2h(d.x, h0, m0); split2h(d.y, h1, m1);
        split2h(d.z, h2, m2); split2h(d.w, h3, m3);
        *(__half2*)(resh + ro)     = __halves2half2(h0, h1);
        *(__half2*)(resh + ro + 2) = __halves2half2(h2, h3);
        *(__half2*)(resm + ro)     = __halves2half2(m0, m1);
        *(__half2*)(resm + ro + 2) = __halves2half2(m2, m3);
    }
    float4 qn;
    if (mode == 0) {
        qn = c;
    } else {
        float4 qo = *(const float4*)(qf + ro);
        qn.x = qo.x + c.x; qn.y = qo.y + c.y; qn.z = qo.z + c.z; qn.w = qo.w + c.w;
    }
    if (mode != 2) {
        *(float4*)(qf + ro) = qn;
    } else {
        __half h0, m0, h1, m1, h2, m2, h3, m3;
        split2h(qn.x, h0, m0); split2h(qn.y, h1, m1);
        split2h(qn.z, h2, m2); split2h(qn.w, h3, m3);
        *(__half2*)(qh + ro)     = __halves2half2(h0, h1);
        *(__half2*)(qh + ro + 2) = __halves2half2(h2, h3);
        *(__half2*)(qm + ro)     = __halves2half2(m0, m1);
        *(__half2*)(qm + ro + 2) = __halves2half2(m2, m3);
    }
    if (lane == 0 && idxf) idxf[(size_t)row * 4 + lvl] = (float)cd;
    float s = d.x * d.x + d.y * d.y + d.z * d.z + d.w * d.w;
    s = blockReduce256(s, sbuf);
    if (threadIdx.x == 0) atomicAdd(commit, s);
}

__global__ void finalize_kernel(const float* __restrict__ a, float* __restrict__ out) {
    out[0] = a[0] * (1.f / ((float)NROWS * IN_DIM))
           + 0.25f * a[1] * (1.f / ((float)NROWS * OUT_DIM));
}

// ---------------- fp16-split GEMM on mma.sync (HMMA) ----------------
// Block tile M=128 x N=128, 256 threads (8 warps), warp tile 32x64, K-step 16,
// 3-stage cp.async pipeline, 2 CTAs/SM.
// Stage layout (24576B): Ah[128r x 48B]=6144 | Am=6144 | Bh[128r x 48B]=6144 | Bm=6144
// NT=3: D = Ah*Bh + Ah*Bm + Am*Bh.  NT=2: D = Ah*Bh + Ah*Bm (A-mid skipped entirely).
// MODE 0: relu(D+bias) -> Oh (and Om if non-null)
// MODE 1: c=D+bias -> Oh, Om (hi/mid split only)
// MODE 2: c=D+bias -> Of, partial += (c-aux)^2 -> accum
// MODE 3: per-block argmin over this block's nct*128 codes of aux[col]-2*D;
//         partials written to Of (=pbV) / idxOut (=pbI) at [blockIdx.x * NROWS + row]
#define STAGE_B 24576
#define SMEM_MMA (3 * STAGE_B)

template <int MODE, int NT>
__global__ __launch_bounds__(256, 2)
void mma_gemm(int K, int Nout, int nct,
              const __half* __restrict__ Ah, const __half* __restrict__ Am,
              const __half* __restrict__ Bh, const __half* __restrict__ Bm,
              const float* __restrict__ bias,
              float* __restrict__ Of, __half* __restrict__ Oh, __half* __restrict__ Om,
              const float* __restrict__ aux, float* __restrict__ accum,
              int* __restrict__ idxOut) {
    extern __shared__ char dsm[];
    __shared__ float sred[8];
    uint32_t smb = smem_u32(dsm);
    int tid = threadIdx.x, lane = tid & 31, wid = tid >> 5;
    int bm = blockIdx.y * 128;
    int bn0 = blockIdx.x * 128 * nct;
    int wm = (wid & 3) * 32, wn = (wid >> 2) * 64;

    const __half* Abh = Ah + (size_t)bm * K;
    const __half* Abm = Am + (size_t)bm * K;

    // --- cp.async role: thread tid loads chunk tid of each of Ah/Am/Bh/Bm ---
    int crow = tid >> 1, csub = tid & 1;
    uint32_t cdst = (uint32_t)(crow * 48 + csub * 16);
    size_t csrc = (size_t)crow * K + csub * 8;

    uint32_t aoffA = (uint32_t)((wm + (lane & 15)) * 48 + ((lane >> 4) & 1) * 16);
    uint32_t aoffB = (uint32_t)(12288 + (wn + (lane & 7) + ((lane >> 4) & 1) * 8) * 48
                                + ((lane >> 3) & 1) * 16);

    float bestV[4];
    int bestI[4];
#pragma unroll
    for (int i = 0; i < 4; i++) { bestV[i] = 3.4e38f; bestI[i] = 0; }
    float partial = 0.f;
    int nk = K >> 4;

    for (int ct = 0; ct < nct; ct++) {
        const __half* Bth = Bh + (size_t)(bn0 + ct * 128) * K;
        const __half* Btm = Bm + (size_t)(bn0 + ct * 128) * K;
        float c[2][8][4];
#pragma unroll
        for (int mt = 0; mt < 2; mt++)
#pragma unroll
            for (int nt = 0; nt < 8; nt++)
#pragma unroll
                for (int k = 0; k < 4; k++) c[mt][nt][k] = 0.f;

        __syncthreads();  // previous ct done with smem
        // prologue: stages 0,1
#pragma unroll
        for (int s = 0; s < 2; s++) {
            uint32_t sb = smb + s * STAGE_B;
            int ko = s * 16;
            CP16(sb + cdst,         (const void*)(Abh + csrc + ko));
            if (NT == 3)
                CP16(sb + 6144 + cdst,  (const void*)(Abm + csrc + ko));
            CP16(sb + 12288 + cdst, (const void*)(Bth + csrc + ko));
            CP16(sb + 18432 + cdst, (const void*)(Btm + csrc + ko));
            CP_COMMIT();
        }

        for (int kt = 0; kt < nk; kt++) {
            int s = kt % 3;
            CP_WAIT1();
            __syncthreads();
            if (kt + 2 < nk) {
                uint32_t sb = smb + ((kt + 2) % 3) * STAGE_B;
                int ko = (kt + 2) * 16;
                CP16(sb + cdst,         (const void*)(Abh + csrc + ko));
                if (NT == 3)
                    CP16(sb + 6144 + cdst,  (const void*)(Abm + csrc + ko));
                CP16(sb + 12288 + cdst, (const void*)(Bth + csrc + ko));
                CP16(sb + 18432 + cdst, (const void*)(Btm + csrc + ko));
            }
            CP_COMMIT();

            uint32_t sb = smb + s * STAGE_B;
            uint32_t ah[2][4], am[2][4];
#pragma unroll
            for (int mt = 0; mt < 2; mt++) {
                uint32_t ad = sb + aoffA + mt * 768;
                LDMX4(ah[mt][0], ah[mt][1], ah[mt][2], ah[mt][3], ad);
                if (NT == 3)
                    LDMX4(am[mt][0], am[mt][1], am[mt][2], am[mt][3], ad + 6144);
            }
#pragma unroll
            for (int p = 0; p < 4; p++) {
                uint32_t bh[4], bmf[4];
                uint32_t bd = sb + aoffB + p * 768;
                LDMX4(bh[0], bh[1], bh[2], bh[3], bd);
                LDMX4(bmf[0], bmf[1], bmf[2], bmf[3], bd + 6144);
#pragma unroll
                for (int mt = 0; mt < 2; mt++)
#pragma unroll
                    for (int q = 0; q < 2; q++) {
                        int nt = 2 * p + q;
                        mma16816(c[mt][nt], ah[mt], &bh[2 * q]);
                        mma16816(c[mt][nt], ah[mt], &bmf[2 * q]);
                        if (NT == 3) mma16816(c[mt][nt], am[mt], &bh[2 * q]);
                    }
            }
        }

        // ---------------- epilogue ----------------
        if (MODE == 3) {
#pragma unroll
            for (int mt = 0; mt < 2; mt++)
#pragma unroll
                for (int nt = 0; nt < 8; nt++) {
                    int colb = bn0 + ct * 128 + wn + nt * 8 + (lane & 3) * 2;
#pragma unroll
                    for (int h = 0; h < 2; h++) {
                        int slot = mt * 2 + h;
#pragma unroll
                        for (int j = 0; j < 2; j++) {
                            float v = aux[colb + j] - 2.f * c[mt][nt][h * 2 + j];
                            if (v < bestV[slot]) { bestV[slot] = v; bestI[slot] = colb + j; }
                        }
                    }
                }
        } else {
#pragma unroll
            for (int mt = 0; mt < 2; mt++)
#pragma unroll
                for (int h = 0; h < 2; h++) {
                    int row = bm + wm + mt * 16 + (lane >> 2) + h * 8;
#pragma unroll
                    for (int nt = 0; nt < 8; nt++) {
                        int col = bn0 + ct * 128 + wn + nt * 8 + (lane & 3) * 2;
                        float v0 = c[mt][nt][h * 2 + 0] + bias[col];
                        float v1 = c[mt][nt][h * 2 + 1] + bias[col + 1];
                        size_t o = (size_t)row * Nout + col;
                        if (MODE == 0) {
                            v0 = fmaxf(v0, 0.f); v1 = fmaxf(v1, 0.f);
                            __half h0, m0, h1x, m1x;
                            split2h(v0, h0, m0); split2h(v1, h1x, m1x);
                            *(__half2*)(Oh + o) = __halves2half2(h0, h1x);
                            if (Om) *(__half2*)(Om + o) = __halves2half2(m0, m1x);
                        } else if (MODE == 1) {
                            __half h0, m0, h1x, m1x;
                            split2h(v0, h0, m0); split2h(v1, h1x, m1x);
                            *(__half2*)(Oh + o) = __halves2half2(h0, h1x);
                            *(__half2*)(Om + o) = __halves2half2(m0, m1x);
                        } else {  // MODE 2
                            Of[o] = v0; Of[o + 1] = v1;
                            float e0 = v0 - aux[o], e1 = v1 - aux[o + 1];
                            partial += e0 * e0 + e1 * e1;
                        }
                    }
                }
        }
    }

    if (MODE == 3) {
        // quad reduce (cols within quad), first-index tie-break
#pragma unroll
        for (int slot = 0; slot < 4; slot++) {
#pragma unroll
            for (int o = 1; o <= 2; o <<= 1) {
                float ov = __shfl_xor_sync(0xffffffffu, bestV[slot], o);
                int oi = __shfl_xor_sync(0xffffffffu, bestI[slot], o);
                if (ov < bestV[slot] || (ov == bestV[slot] && oi < bestI[slot])) {
                    bestV[slot] = ov; bestI[slot] = oi;
                }
            }
        }
        float* sV = (float*)dsm;          // [128][2]
        int* sI = (int*)(dsm + 1024);     // [128][2]
        __syncthreads();
        if ((lane & 3) == 0) {
            int g = wid >> 2;   // n-warp group: wn 0 or 64
#pragma unroll
            for (int mt = 0; mt < 2; mt++)
#pragma unroll
                for (int h = 0; h < 2; h++) {
                    int lr = wm + mt * 16 + (lane >> 2) + h * 8;
                    sV[lr * 2 + g] = bestV[mt * 2 + h];
                    sI[lr * 2 + g] = bestI[mt * 2 + h];
                }
        }
        __syncthreads();
        if (tid < 128) {
            float v0 = sV[tid * 2], v1 = sV[tid * 2 + 1];
            int i0 = sI[tid * 2], i1 = sI[tid * 2 + 1];
            if (v1 < v0 || (v1 == v0 && i1 < i0)) { v0 = v1; i0 = i1; }
            size_t po = (size_t)blockIdx.x * NROWS + bm + tid;
            Of[po] = v0;
            idxOut[po] = i0;
        }
    }
    if (MODE == 2) {
        partial = blockReduce256(partial, sred);
        if (tid == 0) atomicAdd(accum, partial);
    }
}

// ---------------- launch ----------------
extern "C" void kernel_launch(void* const* d_in, const int* in_sizes, int n_in,
                              void* d_out, int out_size) {
    const float* x    = (const float*)d_in[0];
    const float* ln_g = (const float*)d_in[1];
    const float* ln_b = (const float*)d_in[2];
    const float* W1   = (const float*)d_in[3];
    const float* b1   = (const float*)d_in[4];
    const float* W2   = (const float*)d_in[5];
    const float* b2   = (const float*)d_in[6];
    const float* Wd1  = (const float*)d_in[7];
    const float* bd1  = (const float*)d_in[8];
    const float* Wd2  = (const float*)d_in[9];
    const float* bd2  = (const float*)d_in[10];
    const float* cbs  = (const float*)d_in[11];
    float* out = (float*)d_out;

    __half *a0h, *a0m, *h1h, *h1m, *resh, *resm, *wth, *wtm, *cbh, *cbm;
    float *qf, *cnorm, *accum, *pbV;
    int *pbI;
    cudaGetSymbolAddress((void**)&a0h,  g_a0h);
    cudaGetSymbolAddress((void**)&a0m,  g_a0m);
    cudaGetSymbolAddress((void**)&h1h,  g_h1h);
    cudaGetSymbolAddress((void**)&h1m,  g_h1m);
    cudaGetSymbolAddress((void**)&resh, g_resh);
    cudaGetSymbolAddress((void**)&resm, g_resm);
    cudaGetSymbolAddress((void**)&qf,   g_qf);
    cudaGetSymbolAddress((void**)&wth,  g_wth);
    cudaGetSymbolAddress((void**)&wtm,  g_wtm);
    cudaGetSymbolAddress((void**)&cbh,  g_cbh);
    cudaGetSymbolAddress((void**)&cbm,  g_cbm);
    cudaGetSymbolAddress((void**)&pbV,  g_pbV);
    cudaGetSymbolAddress((void**)&pbI,  g_pbI);
    cudaGetSymbolAddress((void**)&cnorm, g_cnorm);
    cudaGetSymbolAddress((void**)&accum, g_accum);

    cudaFuncSetAttribute(mma_gemm<0, 3>, cudaFuncAttributeMaxDynamicSharedMemorySize, SMEM_MMA);
    cudaFuncSetAttribute(mma_gemm<0, 2>, cudaFuncAttributeMaxDynamicSharedMemorySize, SMEM_MMA);
    cudaFuncSetAttribute(mma_gemm<1, 3>, cudaFuncAttributeMaxDynamicSharedMemorySize, SMEM_MMA);
    cudaFuncSetAttribute(mma_gemm<2, 2>, cudaFuncAttributeMaxDynamicSharedMemorySize, SMEM_MMA);
    cudaFuncSetAttribute(mma_gemm<3, 3>, cudaFuncAttributeMaxDynamicSharedMemorySize, SMEM_MMA);

    const size_t reconElems = (size_t)NROWS * IN_DIM;
    size_t reconOff = ((size_t)out_size == reconElems) ? 0 : 1;
    bool fullOut = ((size_t)out_size >= 1 + reconElems + (size_t)NROWS * 4);
    float* idxf = fullOut ? (out + 1 + reconElems) : nullptr;

    // Launch order: enc1 is launch #4 here = ncu's captured launch (offset +2).
    ln_kernel<<<NROWS, 256>>>(x, ln_g, ln_b, a0h, a0m);                        // 1
    wsplit_kernel<<<(768 * 256 + 255) / 256, 256>>>(W1, wth, wtm, 768, 256);   // 2
    zero_kernel<<<1, 32>>>(accum);                                             // 3
    // 4: encoder GEMM1 (target of ncu capture)
    mma_gemm<0, 3><<<dim3(2, 512), 256, SMEM_MMA>>>(768, 256, 1, a0h, a0m, wth, wtm, b1,
                                                    nullptr, h1h, h1m, nullptr, nullptr, nullptr);
    wsplit_kernel<<<(256 * 256 + 255) / 256, 256>>>(W2, wth + 196608, wtm + 196608, 256, 256);
    mma_gemm<1, 3><<<dim3(2, 512), 256, SMEM_MMA>>>(256, 256, 1, h1h, h1m,
                                                    wth + 196608, wtm + 196608, b2,
                                                    nullptr, resh, resm, nullptr, nullptr, nullptr);
    cbsplit_kernel<<<(NLEV * KCODES * OUT_DIM) / 256, 256>>>(cbs, cbh, cbm);
    cnorm_kernel<<<(NLEV * KCODES * 32) / 256, 256>>>(cbs, cnorm);

    // residual quantization: dist split across 8 codebook tiles (grid.x),
    // then fused combine+update (q splits land in h1h/h1m on last level)
    for (int l = 0; l < NLEV; l++) {
        mma_gemm<3, 3><<<dim3(8, 512), 256, SMEM_MMA>>>(256, 0, 1, resh, resm,
                                                        cbh + (size_t)l * KCODES * OUT_DIM,
                                                        cbm + (size_t)l * KCODES * OUT_DIM,
                                                        nullptr, pbV, nullptr, nullptr,
                                                        cnorm + l * KCODES, nullptr, pbI);
        int mode = (l == 0) ? 0 : ((l == NLEV - 1) ? 2 : 1);
        update_kernel<<<(NROWS * 64) / 256, 256>>>(cbs + (size_t)l * KCODES * OUT_DIM,
                                                   pbV, pbI, resh, resm, qf, h1h, h1m,
                                                   mode, accum + 1, idxf, l);
    }

    // decoder: dec1 2-term (A-mid dropped; d1 stored hi-only), dec2 2-term
    wsplit_kernel<<<(256 * 768 + 255) / 256, 256>>>(Wd1, wth + 262144, wtm + 262144, 256, 768);
    mma_gemm<0, 2><<<dim3(6, 512), 256, SMEM_MMA>>>(256, 768, 1, h1h, h1h,
                                                    wth + 262144, wtm + 262144, bd1,
                                                    nullptr, a0h, nullptr, nullptr, nullptr, nullptr);
    wsplit_kernel<<<(768 * 768 + 255) / 256, 256>>>(Wd2, wth + 458752, wtm + 458752, 768, 768);
    mma_gemm<2, 2><<<dim3(6, 512), 256, SMEM_MMA>>>(768, 768, 1, a0h, a0h,
                                                    wth + 458752, wtm + 458752, bd2,
                                                    out + reconOff, nullptr, nullptr, x, accum, nullptr);

    if (fullOut) {
        finalize_kernel<<<1, 1>>>(accum, out);
    }
}

// round 16
// speedup vs baseline: 1.4894x; 1.0743x over previous
#include <cuda_runtime.h>
#include <cuda_fp16.h>
#include <cstdint>

#define NROWS   65536
#define IN_DIM  768
#define OUT_DIM 256
#define NLEV    4
#define KCODES  1024

// ---------------- device scratch ----------------
__device__ __align__(256) __half g_a0h[(size_t)NROWS * IN_DIM];   // xn hi; later d1 hi
__device__ __align__(256) __half g_a0m[(size_t)NROWS * IN_DIM];   // xn mid
__device__ __align__(256) __half g_h1h[(size_t)NROWS * OUT_DIM];  // h1 hi; later q hi
__device__ __align__(256) __half g_h1m[(size_t)NROWS * OUT_DIM];  // h1 mid; later q mid
__device__ __align__(256) __half g_resh[(size_t)NROWS * OUT_DIM]; // residual hi (authoritative)
__device__ __align__(256) __half g_resm[(size_t)NROWS * OUT_DIM]; // residual mid
__device__ __align__(256) float  g_qf [(size_t)NROWS * OUT_DIM];
__device__ __align__(256) __half g_wth[1048576];                  // transposed hi weights (packed)
__device__ __align__(256) __half g_wtm[1048576];                  // transposed mid weights
__device__ __align__(256) __half g_cbh[(size_t)NLEV * KCODES * OUT_DIM];
__device__ __align__(256) __half g_cbm[(size_t)NLEV * KCODES * OUT_DIM];
__device__ __align__(256) float  g_pbV[(size_t)8 * NROWS];        // per-tile argmin partials
__device__ __align__(256) int    g_pbI[(size_t)8 * NROWS];
__device__ float g_cnorm[NLEV * KCODES];
__device__ float g_accum[8];

// ---------------- helpers ----------------
__device__ __forceinline__ uint32_t smem_u32(const void* p) {
    uint32_t a;
    asm("{ .reg .u64 t; cvta.to.shared.u64 t, %1; cvt.u32.u64 %0, t; }" : "=r"(a) : "l"(p));
    return a;
}
__device__ __forceinline__ void split2h(float v, __half& h, __half& m) {
    h = __float2half_rn(v);
    m = __float2half_rn(v - __half2float(h));
}

#define CP16(dst, src)  asm volatile("cp.async.cg.shared.global [%0], [%1], 16;" :: "r"(dst), "l"(src) : "memory")
#define CP_COMMIT()     asm volatile("cp.async.commit_group;" ::: "memory")
#define CP_WAIT1()      asm volatile("cp.async.wait_group 1;" ::: "memory")

#define LDMX4(r0, r1, r2, r3, addr) \
    asm volatile("ldmatrix.sync.aligned.m8n8.x4.shared.b16 {%0,%1,%2,%3}, [%4];" \
                 : "=r"(r0), "=r"(r1), "=r"(r2), "=r"(r3) : "r"(addr))

__device__ __forceinline__ void mma16816(float* c, const uint32_t* a, const uint32_t* b) {
    asm volatile(
        "mma.sync.aligned.m16n8k16.row.col.f32.f16.f16.f32 "
        "{%0,%1,%2,%3}, {%4,%5,%6,%7}, {%8,%9}, {%0,%1,%2,%3};"
        : "+f"(c[0]), "+f"(c[1]), "+f"(c[2]), "+f"(c[3])
        : "r"(a[0]), "r"(a[1]), "r"(a[2]), "r"(a[3]), "r"(b[0]), "r"(b[1]));
}

__device__ __forceinline__ float blockReduce256(float v, float* sbuf) {
    int tid = threadIdx.x;
#pragma unroll
    for (int o = 16; o > 0; o >>= 1) v += __shfl_down_sync(0xffffffffu, v, o);
    __syncthreads();
    if ((tid & 31) == 0) sbuf[tid >> 5] = v;
    __syncthreads();
    if (tid < 8) {
        v = sbuf[tid];
#pragma unroll
        for (int o = 4; o > 0; o >>= 1) v += __shfl_down_sync(0xffu, v, o);
    }
    return v;
}

// ---------------- small kernels ----------------
__global__ void zero_kernel(float* a) {
    if (threadIdx.x < 8) a[threadIdx.x] = 0.f;
}

__global__ void ln_kernel(const float* __restrict__ x, const float* __restrict__ g,
                          const float* __restrict__ b,
                          __half* __restrict__ xh, __half* __restrict__ xm) {
    __shared__ float sbuf[8];
    __shared__ float mu_s, rstd_s;
    int row = blockIdx.x, tid = threadIdx.x;
    const float* xr = x + (size_t)row * IN_DIM;
    float v0 = xr[tid], v1 = xr[tid + 256], v2 = xr[tid + 512];
    float s = blockReduce256(v0 + v1 + v2, sbuf);
    if (tid == 0) mu_s = s * (1.f / IN_DIM);
    __syncthreads();
    float mu = mu_s;
    float d0 = v0 - mu, d1 = v1 - mu, d2 = v2 - mu;
    float q = blockReduce256(d0 * d0 + d1 * d1 + d2 * d2, sbuf);
    if (tid == 0) rstd_s = rsqrtf(q * (1.f / IN_DIM) + 1e-5f);
    __syncthreads();
    float rstd = rstd_s;
    size_t o = (size_t)row * IN_DIM;
    __half h, m;
    float y0 = d0 * rstd * g[tid]       + b[tid];
    float y1 = d1 * rstd * g[tid + 256] + b[tid + 256];
    float y2 = d2 * rstd * g[tid + 512] + b[tid + 512];
    split2h(y0, h, m); xh[o + tid]       = h; xm[o + tid]       = m;
    split2h(y1, h, m); xh[o + tid + 256] = h; xm[o + tid + 256] = m;
    split2h(y2, h, m); xh[o + tid + 512] = h; xm[o + tid + 512] = m;
}

// transpose + split: W [K,N] row-major -> Bh/Bm [N,K] half
__global__ void wsplit_kernel(const float* __restrict__ W, __half* __restrict__ Bh,
                              __half* __restrict__ Bm, int K, int N) {
    int i = blockIdx.x * 256 + threadIdx.x;
    if (i >= K * N) return;
    int k = i / N, n = i % N;
    __half h, m;
    split2h(W[i], h, m);
    Bh[(size_t)n * K + k] = h;
    Bm[(size_t)n * K + k] = m;
}

__global__ void cbsplit_kernel(const float* __restrict__ cb, __half* __restrict__ h,
                               __half* __restrict__ m) {
    size_t i = (size_t)blockIdx.x * 256 + threadIdx.x;
    __half hh, mm;
    split2h(cb[i], hh, mm);
    h[i] = hh; m[i] = mm;
}

__global__ void cnorm_kernel(const float* __restrict__ cb, float* __restrict__ cn) {
    int gw = (blockIdx.x * blockDim.x + threadIdx.x) >> 5;
    int lane = threadIdx.x & 31;
    if (gw >= NLEV * KCODES) return;
    const float4* c = (const float4*)(cb + (size_t)gw * OUT_DIM);
    float s = 0.f;
#pragma unroll
    for (int i = 0; i < 2; i++) {
        float4 v = c[lane + i * 32];
        s += v.x * v.x + v.y * v.y + v.z * v.z + v.w * v.w;
    }
#pragma unroll
    for (int o = 16; o > 0; o >>= 1) s += __shfl_down_sync(0xffffffffu, s, o);
    if (lane == 0) cn[gw] = s;
}

// fused combine + residual update:
// merge 8 per-tile argmin partials (ascending tile order, first-index tie-break),
// then d = r - cb[code], re-split; q accumulate; commit loss; idx output.
// mode 0=first level, 1=middle, 2=last (writes q splits to qh/qm instead)
__global__ void update_kernel(const float* __restrict__ cb,
                              const float* __restrict__ pbV, const int* __restrict__ pbI,
                              __half* __restrict__ resh, __half* __restrict__ resm,
                              float* __restrict__ qf,
                              __half* __restrict__ qh, __half* __restrict__ qm,
                              int mode, float* __restrict__ commit,
                              float* __restrict__ idxf, int lvl) {
    __shared__ float sbuf[8];
    int tt = blockIdx.x * 256 + threadIdx.x;
    int row = tt >> 6, lane = tt & 63;
    // inline 8-way partial merge (same order/comparison as R11's combine_kernel)
    float bv = pbV[row];
    int bi = pbI[row];
#pragma unroll
    for (int j = 1; j < 8; j++) {
        float v = pbV[(size_t)j * NROWS + row];
        int ii = pbI[(size_t)j * NROWS + row];
        if (v < bv || (v == bv && ii < bi)) { bv = v; bi = ii; }
    }
    int cd = bi;
    size_t ro = (size_t)row * OUT_DIM + lane * 4;
    float4 c = *(const float4*)(cb + (size_t)cd * OUT_DIM + lane * 4);
    __half2 rh01 = *(const __half2*)(resh + ro), rh23 = *(const __half2*)(resh + ro + 2);
    __half2 rm01 = *(const __half2*)(resm + ro), rm23 = *(const __half2*)(resm + ro + 2);
    float4 r;
    r.x = __half2float(__low2half(rh01))  + __half2float(__low2half(rm01));
    r.y = __half2float(__high2half(rh01)) + __half2float(__high2half(rm01));
    r.z = __half2float(__low2half(rh23))  + __half2float(__low2half(rm23));
    r.w = __half2float(__high2half(rh23)) + __half2float(__high2half(rm23));
    float4 d;
    d.x = r.x - c.x; d.y = r.y - c.y; d.z = r.z - c.z; d.w = r.w - c.w;
    if (mode != 2) {
        __half h0, m0, h1, m1, h2, m2, h3, m3;
        split2h(d.x, h0, m0); split2h(d.y, h1, m1);
        split2h(d.z, h2, m2); split2h(d.w, h3, m3);
        *(__half2*)(resh + ro)     = __halves2half2(h0, h1);
        *(__half2*)(resh + ro + 2) = __halves2half2(h2, h3);
        *(__half2*)(resm + ro)     = __halves2half2(m0, m1);
        *(__half2*)(resm + ro + 2) = __halves2half2(m2, m3);
    }
    float4 qn;
    if (mode == 0) {
        qn = c;
    } else {
        float4 qo = *(const float4*)(qf + ro);
        qn.x = qo.x + c.x; qn.y = qo.y + c.y; qn.z = qo.z + c.z; qn.w = qo.w + c.w;
    }
    if (mode != 2) {
        *(float4*)(qf + ro) = qn;
    } else {
        __half h0, m0, h1, m1, h2, m2, h3, m3;
        split2h(qn.x, h0, m0); split2h(qn.y, h1, m1);
        split2h(qn.z, h2, m2); split2h(qn.w, h3, m3);
        *(__half2*)(qh + ro)     = __halves2half2(h0, h1);
        *(__half2*)(qh + ro + 2) = __halves2half2(h2, h3);
        *(__half2*)(qm + ro)     = __halves2half2(m0, m1);
        *(__half2*)(qm + ro + 2) = __halves2half2(m2, m3);
    }
    if (lane == 0 && idxf) idxf[(size_t)row * 4 + lvl] = (float)cd;
    float s = d.x * d.x + d.y * d.y + d.z * d.z + d.w * d.w;
    s = blockReduce256(s, sbuf);
    if (threadIdx.x == 0) atomicAdd(commit, s);
}

__global__ void finalize_kernel(const float* __restrict__ a, float* __restrict__ out) {
    out[0] = a[0] * (1.f / ((float)NROWS * IN_DIM))
           + 0.25f * a[1] * (1.f / ((float)NROWS * OUT_DIM));
}

// ---------------- fp16-split GEMM on mma.sync (HMMA) ----------------
// Block tile M=128 x N=128, 256 threads (8 warps), warp tile 32x64, K-step 16,
// 3-stage cp.async pipeline, 2 CTAs/SM.
// Stage layout (24576B): Ah[128r x 48B]=6144 | Am=6144 | Bh[128r x 48B]=6144 | Bm=6144
// NT=3: D = Ah*Bh + Ah*Bm + Am*Bh.  NT=2: D = Ah*Bh + Ah*Bm.  NT=1: D = Ah*Bh.
// MODE 0: relu(D+bias) -> Oh (and Om if non-null)
// MODE 1: c=D+bias -> Oh, Om (hi/mid split only)
// MODE 2: c=D+bias -> Of, partial += (c-aux)^2 -> accum
// MODE 3: per-block argmin over this block's nct*128 codes of aux[col]-2*D;
//         partials written to Of (=pbV) / idxOut (=pbI) at [blockIdx.x * NROWS + row]
#define STAGE_B 24576
#define SMEM_MMA (3 * STAGE_B)

template <int MODE, int NT>
__global__ __launch_bounds__(256, 2)
void mma_gemm(int K, int Nout, int nct,
              const __half* __restrict__ Ah, const __half* __restrict__ Am,
              const __half* __restrict__ Bh, const __half* __restrict__ Bm,
              const float* __restrict__ bias,
              float* __restrict__ Of, __half* __restrict__ Oh, __half* __restrict__ Om,
              const float* __restrict__ aux, float* __restrict__ accum,
              int* __restrict__ idxOut) {
    extern __shared__ char dsm[];
    __shared__ float sred[8];
    uint32_t smb = smem_u32(dsm);
    int tid = threadIdx.x, lane = tid & 31, wid = tid >> 5;
    int bm = blockIdx.y * 128;
    int bn0 = blockIdx.x * 128 * nct;
    int wm = (wid & 3) * 32, wn = (wid >> 2) * 64;

    const __half* Abh = Ah + (size_t)bm * K;
    const __half* Abm = Am + (size_t)bm * K;

    // --- cp.async role: thread tid loads chunk tid of each of Ah/Am/Bh/Bm ---
    int crow = tid >> 1, csub = tid & 1;
    uint32_t cdst = (uint32_t)(crow * 48 + csub * 16);
    size_t csrc = (size_t)crow * K + csub * 8;

    uint32_t aoffA = (uint32_t)((wm + (lane & 15)) * 48 + ((lane >> 4) & 1) * 16);
    uint32_t aoffB = (uint32_t)(12288 + (wn + (lane & 7) + ((lane >> 4) & 1) * 8) * 48
                                + ((lane >> 3) & 1) * 16);

    float bestV[4];
    int bestI[4];
#pragma unroll
    for (int i = 0; i < 4; i++) { bestV[i] = 3.4e38f; bestI[i] = 0; }
    float partial = 0.f;
    int nk = K >> 4;

    for (int ct = 0; ct < nct; ct++) {
        const __half* Bth = Bh + (size_t)(bn0 + ct * 128) * K;
        const __half* Btm = Bm + (size_t)(bn0 + ct * 128) * K;
        float c[2][8][4];
#pragma unroll
        for (int mt = 0; mt < 2; mt++)
#pragma unroll
            for (int nt = 0; nt < 8; nt++)
#pragma unroll
                for (int k = 0; k < 4; k++) c[mt][nt][k] = 0.f;

        __syncthreads();  // previous ct done with smem
        // prologue: stages 0,1
#pragma unroll
        for (int s = 0; s < 2; s++) {
            uint32_t sb = smb + s * STAGE_B;
            int ko = s * 16;
            CP16(sb + cdst,         (const void*)(Abh + csrc + ko));
            if (NT == 3)
                CP16(sb + 6144 + cdst,  (const void*)(Abm + csrc + ko));
            CP16(sb + 12288 + cdst, (const void*)(Bth + csrc + ko));
            if (NT >= 2)
                CP16(sb + 18432 + cdst, (const void*)(Btm + csrc + ko));
            CP_COMMIT();
        }

        for (int kt = 0; kt < nk; kt++) {
            int s = kt % 3;
            CP_WAIT1();
            __syncthreads();
            if (kt + 2 < nk) {
                uint32_t sb = smb + ((kt + 2) % 3) * STAGE_B;
                int ko = (kt + 2) * 16;
                CP16(sb + cdst,         (const void*)(Abh + csrc + ko));
                if (NT == 3)
                    CP16(sb + 6144 + cdst,  (const void*)(Abm + csrc + ko));
                CP16(sb + 12288 + cdst, (const void*)(Bth + csrc + ko));
                if (NT >= 2)
                    CP16(sb + 18432 + cdst, (const void*)(Btm + csrc + ko));
            }
            CP_COMMIT();

            uint32_t sb = smb + s * STAGE_B;
            uint32_t ah[2][4], am[2][4];
#pragma unroll
            for (int mt = 0; mt < 2; mt++) {
                uint32_t ad = sb + aoffA + mt * 768;
                LDMX4(ah[mt][0], ah[mt][1], ah[mt][2], ah[mt][3], ad);
                if (NT == 3)
                    LDMX4(am[mt][0], am[mt][1], am[mt][2], am[mt][3], ad + 6144);
            }
#pragma unroll
            for (int p = 0; p < 4; p++) {
                uint32_t bh[4], bmf[4];
                uint32_t bd = sb + aoffB + p * 768;
                LDMX4(bh[0], bh[1], bh[2], bh[3], bd);
                if (NT >= 2)
                    LDMX4(bmf[0], bmf[1], bmf[2], bmf[3], bd + 6144);
#pragma unroll
                for (int mt = 0; mt < 2; mt++)
#pragma unroll
                    for (int q = 0; q < 2; q++) {
                        int nt = 2 * p + q;
                        mma16816(c[mt][nt], ah[mt], &bh[2 * q]);
                        if (NT >= 2) mma16816(c[mt][nt], ah[mt], &bmf[2 * q]);
                        if (NT == 3) mma16816(c[mt][nt], am[mt], &bh[2 * q]);
                    }
            }
        }

        // ---------------- epilogue ----------------
        if (MODE == 3) {
#pragma unroll
            for (int mt = 0; mt < 2; mt++)
#pragma unroll
                for (int nt = 0; nt < 8; nt++) {
                    int colb = bn0 + ct * 128 + wn + nt * 8 + (lane & 3) * 2;
#pragma unroll
                    for (int h = 0; h < 2; h++) {
                        int slot = mt * 2 + h;
#pragma unroll
                        for (int j = 0; j < 2; j++) {
                            float v = aux[colb + j] - 2.f * c[mt][nt][h * 2 + j];
                            if (v < bestV[slot]) { bestV[slot] = v; bestI[slot] = colb + j; }
                        }
                    }
                }
        } else {
#pragma unroll
            for (int mt = 0; mt < 2; mt++)
#pragma unroll
                for (int h = 0; h < 2; h++) {
                    int row = bm + wm + mt * 16 + (lane >> 2) + h * 8;
#pragma unroll
                    for (int nt = 0; nt < 8; nt++) {
                        int col = bn0 + ct * 128 + wn + nt * 8 + (lane & 3) * 2;
                        float v0 = c[mt][nt][h * 2 + 0] + bias[col];
                        float v1 = c[mt][nt][h * 2 + 1] + bias[col + 1];
                        size_t o = (size_t)row * Nout + col;
                        if (MODE == 0) {
                            v0 = fmaxf(v0, 0.f); v1 = fmaxf(v1, 0.f);
                            __half h0, m0, h1x, m1x;
                            split2h(v0, h0, m0); split2h(v1, h1x, m1x);
                            *(__half2*)(Oh + o) = __halves2half2(h0, h1x);
                            if (Om) *(__half2*)(Om + o) = __halves2half2(m0, m1x);
                        } else if (MODE == 1) {
                            __half h0, m0, h1x, m1x;
                            split2h(v0, h0, m0); split2h(v1, h1x, m1x);
                            *(__half2*)(Oh + o) = __halves2half2(h0, h1x);
                            *(__half2*)(Om + o) = __halves2half2(m0, m1x);
                        } else {  // MODE 2
                            Of[o] = v0; Of[o + 1] = v1;
                            float e0 = v0 - aux[o], e1 = v1 - aux[o + 1];
                            partial += e0 * e0 + e1 * e1;
                        }
                    }
                }
        }
    }

    if (MODE == 3) {
        // quad reduce (cols within quad), first-index tie-break
#pragma unroll
        for (int slot = 0; slot < 4; slot++) {
#pragma unroll
            for (int o = 1; o <= 2; o <<= 1) {
                float ov = __shfl_xor_sync(0xffffffffu, bestV[slot], o);
                int oi = __shfl_xor_sync(0xffffffffu, bestI[slot], o);
                if (ov < bestV[slot] || (ov == bestV[slot] && oi < bestI[slot])) {
                    bestV[slot] = ov; bestI[slot] = oi;
                }
            }
        }
        float* sV = (float*)dsm;          // [128][2]
        int* sI = (int*)(dsm + 1024);     // [128][2]
        __syncthreads();
        if ((lane & 3) == 0) {
            int g = wid >> 2;   // n-warp group: wn 0 or 64
#pragma unroll
            for (int mt = 0; mt < 2; mt++)
#pragma unroll
                for (int h = 0; h < 2; h++) {
                    int lr = wm + mt * 16 + (lane >> 2) + h * 8;
                    sV[lr * 2 + g] = bestV[mt * 2 + h];
                    sI[lr * 2 + g] = bestI[mt * 2 + h];
                }
        }
        __syncthreads();
        if (tid < 128) {
            float v0 = sV[tid * 2], v1 = sV[tid * 2 + 1];
            int i0 = sI[tid * 2], i1 = sI[tid * 2 + 1];
            if (v1 < v0 || (v1 == v0 && i1 < i0)) { v0 = v1; i0 = i1; }
            size_t po = (size_t)blockIdx.x * NROWS + bm + tid;
            Of[po] = v0;
            idxOut[po] = i0;
        }
    }
    if (MODE == 2) {
        partial = blockReduce256(partial, sred);
        if (tid == 0) atomicAdd(accum, partial);
    }
}

// ---------------- launch ----------------
extern "C" void kernel_launch(void* const* d_in, const int* in_sizes, int n_in,
                              void* d_out, int out_size) {
    const float* x    = (const float*)d_in[0];
    const float* ln_g = (const float*)d_in[1];
    const float* ln_b = (const float*)d_in[2];
    const float* W1   = (const float*)d_in[3];
    const float* b1   = (const float*)d_in[4];
    const float* W2   = (const float*)d_in[5];
    const float* b2   = (const float*)d_in[6];
    const float* Wd1  = (const float*)d_in[7];
    const float* bd1  = (const float*)d_in[8];
    const float* Wd2  = (const float*)d_in[9];
    const float* bd2  = (const float*)d_in[10];
    const float* cbs  = (const float*)d_in[11];
    float* out = (float*)d_out;

    __half *a0h, *a0m, *h1h, *h1m, *resh, *resm, *wth, *wtm, *cbh, *cbm;
    float *qf, *cnorm, *accum, *pbV;
    int *pbI;
    cudaGetSymbolAddress((void**)&a0h,  g_a0h);
    cudaGetSymbolAddress((void**)&a0m,  g_a0m);
    cudaGetSymbolAddress((void**)&h1h,  g_h1h);
    cudaGetSymbolAddress((void**)&h1m,  g_h1m);
    cudaGetSymbolAddress((void**)&resh, g_resh);
    cudaGetSymbolAddress((void**)&resm, g_resm);
    cudaGetSymbolAddress((void**)&qf,   g_qf);
    cudaGetSymbolAddress((void**)&wth,  g_wth);
    cudaGetSymbolAddress((void**)&wtm,  g_wtm);
    cudaGetSymbolAddress((void**)&cbh,  g_cbh);
    cudaGetSymbolAddress((void**)&cbm,  g_cbm);
    cudaGetSymbolAddress((void**)&pbV,  g_pbV);
    cudaGetSymbolAddress((void**)&pbI,  g_pbI);
    cudaGetSymbolAddress((void**)&cnorm, g_cnorm);
    cudaGetSymbolAddress((void**)&accum, g_accum);

    cudaFuncSetAttribute(mma_gemm<0, 3>, cudaFuncAttributeMaxDynamicSharedMemorySize, SMEM_MMA);
    cudaFuncSetAttribute(mma_gemm<0, 2>, cudaFuncAttributeMaxDynamicSharedMemorySize, SMEM_MMA);
    cudaFuncSetAttribute(mma_gemm<1, 3>, cudaFuncAttributeMaxDynamicSharedMemorySize, SMEM_MMA);
    cudaFuncSetAttribute(mma_gemm<2, 1>, cudaFuncAttributeMaxDynamicSharedMemorySize, SMEM_MMA);
    cudaFuncSetAttribute(mma_gemm<3, 3>, cudaFuncAttributeMaxDynamicSharedMemorySize, SMEM_MMA);

    const size_t reconElems = (size_t)NROWS * IN_DIM;
    size_t reconOff = ((size_t)out_size == reconElems) ? 0 : 1;
    bool fullOut = ((size_t)out_size >= 1 + reconElems + (size_t)NROWS * 4);
    float* idxf = fullOut ? (out + 1 + reconElems) : nullptr;

    // Launch order: enc1 is launch #4 here = ncu's captured launch (offset +2).
    ln_kernel<<<NROWS, 256>>>(x, ln_g, ln_b, a0h, a0m);                        // 1
    wsplit_kernel<<<(768 * 256 + 255) / 256, 256>>>(W1, wth, wtm, 768, 256);   // 2
    zero_kernel<<<1, 32>>>(accum);                                             // 3
    // 4: encoder GEMM1 (target of ncu capture)
    mma_gemm<0, 3><<<dim3(2, 512), 256, SMEM_MMA>>>(768, 256, 1, a0h, a0m, wth, wtm, b1,
                                                    nullptr, h1h, h1m, nullptr, nullptr, nullptr);
    wsplit_kernel<<<(256 * 256 + 255) / 256, 256>>>(W2, wth + 196608, wtm + 196608, 256, 256);
    mma_gemm<1, 3><<<dim3(2, 512), 256, SMEM_MMA>>>(256, 256, 1, h1h, h1m,
                                                    wth + 196608, wtm + 196608, b2,
                                                    nullptr, resh, resm, nullptr, nullptr, nullptr);
    cbsplit_kernel<<<(NLEV * KCODES * OUT_DIM) / 256, 256>>>(cbs, cbh, cbm);
    cnorm_kernel<<<(NLEV * KCODES * 32) / 256, 256>>>(cbs, cnorm);

    // residual quantization: dist split across 8 codebook tiles (grid.x),
    // then fused combine+update (q splits land in h1h/h1m on last level)
    for (int l = 0; l < NLEV; l++) {
        mma_gemm<3, 3><<<dim3(8, 512), 256, SMEM_MMA>>>(256, 0, 1, resh, resm,
                                                        cbh + (size_t)l * KCODES * OUT_DIM,
                                                        cbm + (size_t)l * KCODES * OUT_DIM,
                                                        nullptr, pbV, nullptr, nullptr,
                                                        cnorm + l * KCODES, nullptr, pbI);
        int mode = (l == 0) ? 0 : ((l == NLEV - 1) ? 2 : 1);
        update_kernel<<<(NROWS * 64) / 256, 256>>>(cbs + (size_t)l * KCODES * OUT_DIM,
                                                   pbV, pbI, resh, resm, qf, h1h, h1m,
                                                   mode, accum + 1, idxf, l);
    }

    // decoder: dec1 2-term (A-mid dropped; d1 stored hi-only), dec2 1-term
    wsplit_kernel<<<(256 * 768 + 255) / 256, 256>>>(Wd1, wth + 262144, wtm + 262144, 256, 768);
    mma_gemm<0, 2><<<dim3(6, 512), 256, SMEM_MMA>>>(256, 768, 1, h1h, h1h,
                                                    wth + 262144, wtm + 262144, bd1,
                                                    nullptr, a0h, nullptr, nullptr, nullptr, nullptr);
    wsplit_kernel<<<(768 * 768 + 255) / 256, 256>>>(Wd2, wth + 458752, wtm + 458752, 768, 768);
    mma_gemm<2, 1><<<dim3(6, 512), 256, SMEM_MMA>>>(768, 768, 1, a0h, a0h,
                                                    wth + 458752, wtm + 458752, bd2,
                                                    out + reconOff, nullptr, nullptr, x, accum, nullptr);

    if (fullOut) {
        finalize_kernel<<<1, 1>>>(accum, out);
    }
}

// round 17
// speedup vs baseline: 1.5331x; 1.0293x over previous
#include <cuda_runtime.h>
#include <cuda_fp16.h>
#include <cstdint>

#define NROWS   65536
#define IN_DIM  768
#define OUT_DIM 256
#define NLEV    4
#define KCODES  1024

// ---------------- device scratch ----------------
__device__ __align__(256) __half g_a0h[(size_t)NROWS * IN_DIM];   // xn hi; later d1 hi
__device__ __align__(256) __half g_a0m[(size_t)NROWS * IN_DIM];   // xn mid
__device__ __align__(256) __half g_h1h[(size_t)NROWS * OUT_DIM];  // h1 hi; later q hi
__device__ __align__(256) __half g_h1m[(size_t)NROWS * OUT_DIM];  // h1 mid; later q mid
__device__ __align__(256) __half g_resh[(size_t)NROWS * OUT_DIM]; // residual hi (authoritative)
__device__ __align__(256) __half g_resm[(size_t)NROWS * OUT_DIM]; // residual mid
__device__ __align__(256) float  g_qf [(size_t)NROWS * OUT_DIM];
__device__ __align__(256) __half g_wth[1048576];                  // transposed hi weights (packed)
__device__ __align__(256) __half g_wtm[1048576];                  // transposed mid weights
__device__ __align__(256) __half g_cbh[(size_t)NLEV * KCODES * OUT_DIM];
__device__ __align__(256) __half g_cbm[(size_t)NLEV * KCODES * OUT_DIM];
__device__ __align__(256) float  g_pbV[(size_t)8 * NROWS];        // per-tile argmin partials
__device__ __align__(256) int    g_pbI[(size_t)8 * NROWS];
__device__ float g_cnorm[NLEV * KCODES];
__device__ float g_accum[8];

// ---------------- helpers ----------------
__device__ __forceinline__ uint32_t smem_u32(const void* p) {
    uint32_t a;
    asm("{ .reg .u64 t; cvta.to.shared.u64 t, %1; cvt.u32.u64 %0, t; }" : "=r"(a) : "l"(p));
    return a;
}
__device__ __forceinline__ void split2h(float v, __half& h, __half& m) {
    h = __float2half_rn(v);
    m = __float2half_rn(v - __half2float(h));
}

#define CP16(dst, src)  asm volatile("cp.async.cg.shared.global [%0], [%1], 16;" :: "r"(dst), "l"(src) : "memory")
#define CP_COMMIT()     asm volatile("cp.async.commit_group;" ::: "memory")
#define CP_WAIT1()      asm volatile("cp.async.wait_group 1;" ::: "memory")

#define LDMX4(r0, r1, r2, r3, addr) \
    asm volatile("ldmatrix.sync.aligned.m8n8.x4.shared.b16 {%0,%1,%2,%3}, [%4];" \
                 : "=r"(r0), "=r"(r1), "=r"(r2), "=r"(r3) : "r"(addr))

__device__ __forceinline__ void mma16816(float* c, const uint32_t* a, const uint32_t* b) {
    asm volatile(
        "mma.sync.aligned.m16n8k16.row.col.f32.f16.f16.f32 "
        "{%0,%1,%2,%3}, {%4,%5,%6,%7}, {%8,%9}, {%0,%1,%2,%3};"
        : "+f"(c[0]), "+f"(c[1]), "+f"(c[2]), "+f"(c[3])
        : "r"(a[0]), "r"(a[1]), "r"(a[2]), "r"(a[3]), "r"(b[0]), "r"(b[1]));
}

__device__ __forceinline__ float blockReduce256(float v, float* sbuf) {
    int tid = threadIdx.x;
#pragma unroll
    for (int o = 16; o > 0; o >>= 1) v += __shfl_down_sync(0xffffffffu, v, o);
    __syncthreads();
    if ((tid & 31) == 0) sbuf[tid >> 5] = v;
    __syncthreads();
    if (tid < 8) {
        v = sbuf[tid];
#pragma unroll
        for (int o = 4; o > 0; o >>= 1) v += __shfl_down_sync(0xffu, v, o);
    }
    return v;
}

// ---------------- small kernels ----------------
__global__ void zero_kernel(float* a) {
    if (threadIdx.x < 8) a[threadIdx.x] = 0.f;
}

__global__ void ln_kernel(const float* __restrict__ x, const float* __restrict__ g,
                          const float* __restrict__ b,
                          __half* __restrict__ xh, __half* __restrict__ xm) {
    __shared__ float sbuf[8];
    __shared__ float mu_s, rstd_s;
    int row = blockIdx.x, tid = threadIdx.x;
    const float* xr = x + (size_t)row * IN_DIM;
    float v0 = xr[tid], v1 = xr[tid + 256], v2 = xr[tid + 512];
    float s = blockReduce256(v0 + v1 + v2, sbuf);
    if (tid == 0) mu_s = s * (1.f / IN_DIM);
    __syncthreads();
    float mu = mu_s;
    float d0 = v0 - mu, d1 = v1 - mu, d2 = v2 - mu;
    float q = blockReduce256(d0 * d0 + d1 * d1 + d2 * d2, sbuf);
    if (tid == 0) rstd_s = rsqrtf(q * (1.f / IN_DIM) + 1e-5f);
    __syncthreads();
    float rstd = rstd_s;
    size_t o = (size_t)row * IN_DIM;
    __half h, m;
    float y0 = d0 * rstd * g[tid]       + b[tid];
    float y1 = d1 * rstd * g[tid + 256] + b[tid + 256];
    float y2 = d2 * rstd * g[tid + 512] + b[tid + 512];
    split2h(y0, h, m); xh[o + tid]       = h; xm[o + tid]       = m;
    split2h(y1, h, m); xh[o + tid + 256] = h; xm[o + tid + 256] = m;
    split2h(y2, h, m); xh[o + tid + 512] = h; xm[o + tid + 512] = m;
}

// transpose + split: W [K,N] row-major -> Bh/Bm [N,K] half
__global__ void wsplit_kernel(const float* __restrict__ W, __half* __restrict__ Bh,
                              __half* __restrict__ Bm, int K, int N) {
    int i = blockIdx.x * 256 + threadIdx.x;
    if (i >= K * N) return;
    int k = i / N, n = i % N;
    __half h, m;
    split2h(W[i], h, m);
    Bh[(size_t)n * K + k] = h;
    Bm[(size_t)n * K + k] = m;
}

__global__ void cbsplit_kernel(const float* __restrict__ cb, __half* __restrict__ h,
                               __half* __restrict__ m) {
    size_t i = (size_t)blockIdx.x * 256 + threadIdx.x;
    __half hh, mm;
    split2h(cb[i], hh, mm);
    h[i] = hh; m[i] = mm;
}

__global__ void cnorm_kernel(const float* __restrict__ cb, float* __restrict__ cn) {
    int gw = (blockIdx.x * blockDim.x + threadIdx.x) >> 5;
    int lane = threadIdx.x & 31;
    if (gw >= NLEV * KCODES) return;
    const float4* c = (const float4*)(cb + (size_t)gw * OUT_DIM);
    float s = 0.f;
#pragma unroll
    for (int i = 0; i < 2; i++) {
        float4 v = c[lane + i * 32];
        s += v.x * v.x + v.y * v.y + v.z * v.z + v.w * v.w;
    }
#pragma unroll
    for (int o = 16; o > 0; o >>= 1) s += __shfl_down_sync(0xffffffffu, s, o);
    if (lane == 0) cn[gw] = s;
}

// fused combine + residual update:
// merge 8 per-tile argmin partials (ascending tile order, first-index tie-break),
// then d = r - cb[code], re-split; q accumulate; commit loss; idx output.
// mode 0=first level, 1=middle, 2=last (writes q splits to qh/qm instead)
__global__ void update_kernel(const float* __restrict__ cb,
                              const float* __restrict__ pbV, const int* __restrict__ pbI,
                              __half* __restrict__ resh, __half* __restrict__ resm,
                              float* __restrict__ qf,
                              __half* __restrict__ qh, __half* __restrict__ qm,
                              int mode, float* __restrict__ commit,
                              float* __restrict__ idxf, int lvl) {
    __shared__ float sbuf[8];
    int tt = blockIdx.x * 256 + threadIdx.x;
    int row = tt >> 6, lane = tt & 63;
    // inline 8-way partial merge (same order/comparison as R11's combine_kernel)
    float bv = pbV[row];
    int bi = pbI[row];
#pragma unroll
    for (int j = 1; j < 8; j++) {
        float v = pbV[(size_t)j * NROWS + row];
        int ii = pbI[(size_t)j * NROWS + row];
        if (v < bv || (v == bv && ii < bi)) { bv = v; bi = ii; }
    }
    int cd = bi;
    size_t ro = (size_t)row * OUT_DIM + lane * 4;
    float4 c = *(const float4*)(cb + (size_t)cd * OUT_DIM + lane * 4);
    __half2 rh01 = *(const __half2*)(resh + ro), rh23 = *(const __half2*)(resh + ro + 2);
    __half2 rm01 = *(const __half2*)(resm + ro), rm23 = *(const __half2*)(resm + ro + 2);
    float4 r;
    r.x = __half2float(__low2half(rh01))  + __half2float(__low2half(rm01));
    r.y = __half2float(__high2half(rh01)) + __half2float(__high2half(rm01));
    r.z = __half2float(__low2half(rh23))  + __half2float(__low2half(rm23));
    r.w = __half2float(__high2half(rh23)) + __half2float(__high2half(rm23));
    float4 d;
    d.x = r.x - c.x; d.y = r.y - c.y; d.z = r.z - c.z; d.w = r.w - c.w;
    if (mode != 2) {
        __half h0, m0, h1, m1, h2, m2, h3, m3;
        split2h(d.x, h0, m0); split2h(d.y, h1, m1);
        split2h(d.z, h2, m2); split2h(d.w, h3, m3);
        *(__half2*)(resh + ro)     = __halves2half2(h0, h1);
        *(__half2*)(resh + ro + 2) = __halves2half2(h2, h3);
        *(__half2*)(resm + ro)     = __halves2half2(m0, m1);
        *(__half2*)(resm + ro + 2) = __halves2half2(m2, m3);
    }
    float4 qn;
    if (mode == 0) {
        qn = c;
    } else {
        float4 qo = *(const float4*)(qf + ro);
        qn.x = qo.x + c.x; qn.y = qo.y + c.y; qn.z = qo.z + c.z; qn.w = qo.w + c.w;
    }
    if (mode != 2) {
        *(float4*)(qf + ro) = qn;
    } else {
        __half h0, m0, h1, m1, h2, m2, h3, m3;
        split2h(qn.x, h0, m0); split2h(qn.y, h1, m1);
        split2h(qn.z, h2, m2); split2h(qn.w, h3, m3);
        *(__half2*)(qh + ro)     = __halves2half2(h0, h1);
        *(__half2*)(qh + ro + 2) = __halves2half2(h2, h3);
        *(__half2*)(qm + ro)     = __halves2half2(m0, m1);
        *(__half2*)(qm + ro + 2) = __halves2half2(m2, m3);
    }
    if (lane == 0 && idxf) idxf[(size_t)row * 4 + lvl] = (float)cd;
    float s = d.x * d.x + d.y * d.y + d.z * d.z + d.w * d.w;
    s = blockReduce256(s, sbuf);
    if (threadIdx.x == 0) atomicAdd(commit, s);
}

__global__ void finalize_kernel(const float* __restrict__ a, float* __restrict__ out) {
    out[0] = a[0] * (1.f / ((float)NROWS * IN_DIM))
           + 0.25f * a[1] * (1.f / ((float)NROWS * OUT_DIM));
}

// ---------------- fp16-split GEMM on mma.sync (HMMA) ----------------
// Block tile M=128 x N=128, 256 threads (8 warps), warp tile 32x64, K-step 16,
// 3-stage cp.async pipeline, 2 CTAs/SM.
// Stage layout (24576B): Ah[128r x 48B]=6144 | Am=6144 | Bh[128r x 48B]=6144 | Bm=6144
// NT=3: D = Ah*Bh + Ah*Bm + Am*Bh.  NT=2: D = Ah*Bh + Ah*Bm.  NT=1: D = Ah*Bh.
// MODE 0: relu(D+bias) -> Oh (and Om if non-null)
// MODE 1: c=D+bias -> Oh, Om (hi/mid split only)
// MODE 2: c=D+bias -> Of, partial += (c-aux)^2 -> accum
// MODE 3: per-block argmin over this block's nct*128 codes of aux[col]-2*D;
//         partials written to Of (=pbV) / idxOut (=pbI) at [blockIdx.x * NROWS + row]
#define STAGE_B 24576
#define SMEM_MMA (3 * STAGE_B)

template <int MODE, int NT>
__global__ __launch_bounds__(256, 2)
void mma_gemm(int K, int Nout, int nct,
              const __half* __restrict__ Ah, const __half* __restrict__ Am,
              const __half* __restrict__ Bh, const __half* __restrict__ Bm,
              const float* __restrict__ bias,
              float* __restrict__ Of, __half* __restrict__ Oh, __half* __restrict__ Om,
              const float* __restrict__ aux, float* __restrict__ accum,
              int* __restrict__ idxOut) {
    extern __shared__ char dsm[];
    __shared__ float sred[8];
    uint32_t smb = smem_u32(dsm);
    int tid = threadIdx.x, lane = tid & 31, wid = tid >> 5;
    int bm = blockIdx.y * 128;
    int bn0 = blockIdx.x * 128 * nct;
    int wm = (wid & 3) * 32, wn = (wid >> 2) * 64;

    const __half* Abh = Ah + (size_t)bm * K;
    const __half* Abm = Am + (size_t)bm * K;

    // --- cp.async role: thread tid loads chunk tid of each of Ah/Am/Bh/Bm ---
    int crow = tid >> 1, csub = tid & 1;
    uint32_t cdst = (uint32_t)(crow * 48 + csub * 16);
    size_t csrc = (size_t)crow * K + csub * 8;

    uint32_t aoffA = (uint32_t)((wm + (lane & 15)) * 48 + ((lane >> 4) & 1) * 16);
    uint32_t aoffB = (uint32_t)(12288 + (wn + (lane & 7) + ((lane >> 4) & 1) * 8) * 48
                                + ((lane >> 3) & 1) * 16);

    float bestV[4];
    int bestI[4];
#pragma unroll
    for (int i = 0; i < 4; i++) { bestV[i] = 3.4e38f; bestI[i] = 0; }
    float partial = 0.f;
    int nk = K >> 4;

    for (int ct = 0; ct < nct; ct++) {
        const __half* Bth = Bh + (size_t)(bn0 + ct * 128) * K;
        const __half* Btm = Bm + (size_t)(bn0 + ct * 128) * K;
        float c[2][8][4];
#pragma unroll
        for (int mt = 0; mt < 2; mt++)
#pragma unroll
            for (int nt = 0; nt < 8; nt++)
#pragma unroll
                for (int k = 0; k < 4; k++) c[mt][nt][k] = 0.f;

        __syncthreads();  // previous ct done with smem
        // prologue: stages 0,1
#pragma unroll
        for (int s = 0; s < 2; s++) {
            uint32_t sb = smb + s * STAGE_B;
            int ko = s * 16;
            CP16(sb + cdst,         (const void*)(Abh + csrc + ko));
            if (NT == 3)
                CP16(sb + 6144 + cdst,  (const void*)(Abm + csrc + ko));
            CP16(sb + 12288 + cdst, (const void*)(Bth + csrc + ko));
            if (NT >= 2)
                CP16(sb + 18432 + cdst, (const void*)(Btm + csrc + ko));
            CP_COMMIT();
        }

        for (int kt = 0; kt < nk; kt++) {
            int s = kt % 3;
            CP_WAIT1();
            __syncthreads();
            if (kt + 2 < nk) {
                uint32_t sb = smb + ((kt + 2) % 3) * STAGE_B;
                int ko = (kt + 2) * 16;
                CP16(sb + cdst,         (const void*)(Abh + csrc + ko));
                if (NT == 3)
                    CP16(sb + 6144 + cdst,  (const void*)(Abm + csrc + ko));
                CP16(sb + 12288 + cdst, (const void*)(Bth + csrc + ko));
                if (NT >= 2)
                    CP16(sb + 18432 + cdst, (const void*)(Btm + csrc + ko));
            }
            CP_COMMIT();

            uint32_t sb = smb + s * STAGE_B;
            uint32_t ah[2][4], am[2][4];
#pragma unroll
            for (int mt = 0; mt < 2; mt++) {
                uint32_t ad = sb + aoffA + mt * 768;
                LDMX4(ah[mt][0], ah[mt][1], ah[mt][2], ah[mt][3], ad);
                if (NT == 3)
                    LDMX4(am[mt][0], am[mt][1], am[mt][2], am[mt][3], ad + 6144);
            }
#pragma unroll
            for (int p = 0; p < 4; p++) {
                uint32_t bh[4], bmf[4];
                uint32_t bd = sb + aoffB + p * 768;
                LDMX4(bh[0], bh[1], bh[2], bh[3], bd);
                if (NT >= 2)
                    LDMX4(bmf[0], bmf[1], bmf[2], bmf[3], bd + 6144);
#pragma unroll
                for (int mt = 0; mt < 2; mt++)
#pragma unroll
                    for (int q = 0; q < 2; q++) {
                        int nt = 2 * p + q;
                        mma16816(c[mt][nt], ah[mt], &bh[2 * q]);
                        if (NT >= 2) mma16816(c[mt][nt], ah[mt], &bmf[2 * q]);
                        if (NT == 3) mma16816(c[mt][nt], am[mt], &bh[2 * q]);
                    }
            }
        }

        // ---------------- epilogue ----------------
        if (MODE == 3) {
#pragma unroll
            for (int mt = 0; mt < 2; mt++)
#pragma unroll
                for (int nt = 0; nt < 8; nt++) {
                    int colb = bn0 + ct * 128 + wn + nt * 8 + (lane & 3) * 2;
#pragma unroll
                    for (int h = 0; h < 2; h++) {
                        int slot = mt * 2 + h;
#pragma unroll
                        for (int j = 0; j < 2; j++) {
                            float v = aux[colb + j] - 2.f * c[mt][nt][h * 2 + j];
                            if (v < bestV[slot]) { bestV[slot] = v; bestI[slot] = colb + j; }
                        }
                    }
                }
        } else {
#pragma unroll
            for (int mt = 0; mt < 2; mt++)
#pragma unroll
                for (int h = 0; h < 2; h++) {
                    int row = bm + wm + mt * 16 + (lane >> 2) + h * 8;
#pragma unroll
                    for (int nt = 0; nt < 8; nt++) {
                        int col = bn0 + ct * 128 + wn + nt * 8 + (lane & 3) * 2;
                        float v0 = c[mt][nt][h * 2 + 0] + bias[col];
                        float v1 = c[mt][nt][h * 2 + 1] + bias[col + 1];
                        size_t o = (size_t)row * Nout + col;
                        if (MODE == 0) {
                            v0 = fmaxf(v0, 0.f); v1 = fmaxf(v1, 0.f);
                            __half h0, m0, h1x, m1x;
                            split2h(v0, h0, m0); split2h(v1, h1x, m1x);
                            *(__half2*)(Oh + o) = __halves2half2(h0, h1x);
                            if (Om) *(__half2*)(Om + o) = __halves2half2(m0, m1x);
                        } else if (MODE == 1) {
                            __half h0, m0, h1x, m1x;
                            split2h(v0, h0, m0); split2h(v1, h1x, m1x);
                            *(__half2*)(Oh + o) = __halves2half2(h0, h1x);
                            *(__half2*)(Om + o) = __halves2half2(m0, m1x);
                        } else {  // MODE 2
                            Of[o] = v0; Of[o + 1] = v1;
                            float e0 = v0 - aux[o], e1 = v1 - aux[o + 1];
                            partial += e0 * e0 + e1 * e1;
                        }
                    }
                }
        }
    }

    if (MODE == 3) {
        // quad reduce (cols within quad), first-index tie-break
#pragma unroll
        for (int slot = 0; slot < 4; slot++) {
#pragma unroll
            for (int o = 1; o <= 2; o <<= 1) {
                float ov = __shfl_xor_sync(0xffffffffu, bestV[slot], o);
                int oi = __shfl_xor_sync(0xffffffffu, bestI[slot], o);
                if (ov < bestV[slot] || (ov == bestV[slot] && oi < bestI[slot])) {
                    bestV[slot] = ov; bestI[slot] = oi;
                }
            }
        }
        float* sV = (float*)dsm;          // [128][2]
        int* sI = (int*)(dsm + 1024);     // [128][2]
        __syncthreads();
        if ((lane & 3) == 0) {
            int g = wid >> 2;   // n-warp group: wn 0 or 64
#pragma unroll
            for (int mt = 0; mt < 2; mt++)
#pragma unroll
                for (int h = 0; h < 2; h++) {
                    int lr = wm + mt * 16 + (lane >> 2) + h * 8;
                    sV[lr * 2 + g] = bestV[mt * 2 + h];
                    sI[lr * 2 + g] = bestI[mt * 2 + h];
                }
        }
        __syncthreads();
        if (tid < 128) {
            float v0 = sV[tid * 2], v1 = sV[tid * 2 + 1];
            int i0 = sI[tid * 2], i1 = sI[tid * 2 + 1];
            if (v1 < v0 || (v1 == v0 && i1 < i0)) { v0 = v1; i0 = i1; }
            size_t po = (size_t)blockIdx.x * NROWS + bm + tid;
            Of[po] = v0;
            idxOut[po] = i0;
        }
    }
    if (MODE == 2) {
        partial = blockReduce256(partial, sred);
        if (tid == 0) atomicAdd(accum, partial);
    }
}

// ---------------- launch ----------------
extern "C" void kernel_launch(void* const* d_in, const int* in_sizes, int n_in,
                              void* d_out, int out_size) {
    const float* x    = (const float*)d_in[0];
    const float* ln_g = (const float*)d_in[1];
    const float* ln_b = (const float*)d_in[2];
    const float* W1   = (const float*)d_in[3];
    const float* b1   = (const float*)d_in[4];
    const float* W2   = (const float*)d_in[5];
    const float* b2   = (const float*)d_in[6];
    const float* Wd1  = (const float*)d_in[7];
    const float* bd1  = (const float*)d_in[8];
    const float* Wd2  = (const float*)d_in[9];
    const float* bd2  = (const float*)d_in[10];
    const float* cbs  = (const float*)d_in[11];
    float* out = (float*)d_out;

    __half *a0h, *a0m, *h1h, *h1m, *resh, *resm, *wth, *wtm, *cbh, *cbm;
    float *qf, *cnorm, *accum, *pbV;
    int *pbI;
    cudaGetSymbolAddress((void**)&a0h,  g_a0h);
    cudaGetSymbolAddress((void**)&a0m,  g_a0m);
    cudaGetSymbolAddress((void**)&h1h,  g_h1h);
    cudaGetSymbolAddress((void**)&h1m,  g_h1m);
    cudaGetSymbolAddress((void**)&resh, g_resh);
    cudaGetSymbolAddress((void**)&resm, g_resm);
    cudaGetSymbolAddress((void**)&qf,   g_qf);
    cudaGetSymbolAddress((void**)&wth,  g_wth);
    cudaGetSymbolAddress((void**)&wtm,  g_wtm);
    cudaGetSymbolAddress((void**)&cbh,  g_cbh);
    cudaGetSymbolAddress((void**)&cbm,  g_cbm);
    cudaGetSymbolAddress((void**)&pbV,  g_pbV);
    cudaGetSymbolAddress((void**)&pbI,  g_pbI);
    cudaGetSymbolAddress((void**)&cnorm, g_cnorm);
    cudaGetSymbolAddress((void**)&accum, g_accum);

    cudaFuncSetAttribute(mma_gemm<0, 3>, cudaFuncAttributeMaxDynamicSharedMemorySize, SMEM_MMA);
    cudaFuncSetAttribute(mma_gemm<0, 1>, cudaFuncAttributeMaxDynamicSharedMemorySize, SMEM_MMA);
    cudaFuncSetAttribute(mma_gemm<1, 3>, cudaFuncAttributeMaxDynamicSharedMemorySize, SMEM_MMA);
    cudaFuncSetAttribute(mma_gemm<2, 1>, cudaFuncAttributeMaxDynamicSharedMemorySize, SMEM_MMA);
    cudaFuncSetAttribute(mma_gemm<3, 3>, cudaFuncAttributeMaxDynamicSharedMemorySize, SMEM_MMA);

    const size_t reconElems = (size_t)NROWS * IN_DIM;
    size_t reconOff = ((size_t)out_size == reconElems) ? 0 : 1;
    bool fullOut = ((size_t)out_size >= 1 + reconElems + (size_t)NROWS * 4);
    float* idxf = fullOut ? (out + 1 + reconElems) : nullptr;

    // Launch order: enc1 is launch #4 here = ncu's captured launch (offset +2).
    ln_kernel<<<NROWS, 256>>>(x, ln_g, ln_b, a0h, a0m);                        // 1
    wsplit_kernel<<<(768 * 256 + 255) / 256, 256>>>(W1, wth, wtm, 768, 256);   // 2
    zero_kernel<<<1, 32>>>(accum);                                             // 3
    // 4: encoder GEMM1 (target of ncu capture)
    mma_gemm<0, 3><<<dim3(2, 512), 256, SMEM_MMA>>>(768, 256, 1, a0h, a0m, wth, wtm, b1,
                                                    nullptr, h1h, h1m, nullptr, nullptr, nullptr);
    wsplit_kernel<<<(256 * 256 + 255) / 256, 256>>>(W2, wth + 196608, wtm + 196608, 256, 256);
    mma_gemm<1, 3><<<dim3(2, 512), 256, SMEM_MMA>>>(256, 256, 1, h1h, h1m,
                                                    wth + 196608, wtm + 196608, b2,
                                                    nullptr, resh, resm, nullptr, nullptr, nullptr);
    cbsplit_kernel<<<(NLEV * KCODES * OUT_DIM) / 256, 256>>>(cbs, cbh, cbm);
    cnorm_kernel<<<(NLEV * KCODES * 32) / 256, 256>>>(cbs, cnorm);

    // residual quantization: dist split across 8 codebook tiles (grid.x),
    // then fused combine+update (q splits land in h1h/h1m on last level)
    for (int l = 0; l < NLEV; l++) {
        mma_gemm<3, 3><<<dim3(8, 512), 256, SMEM_MMA>>>(256, 0, 1, resh, resm,
                                                        cbh + (size_t)l * KCODES * OUT_DIM,
                                                        cbm + (size_t)l * KCODES * OUT_DIM,
                                                        nullptr, pbV, nullptr, nullptr,
                                                        cnorm + l * KCODES, nullptr, pbI);
        int mode = (l == 0) ? 0 : ((l == NLEV - 1) ? 2 : 1);
        update_kernel<<<(NROWS * 64) / 256, 256>>>(cbs + (size_t)l * KCODES * OUT_DIM,
                                                   pbV, pbI, resh, resm, qf, h1h, h1m,
                                                   mode, accum + 1, idxf, l);
    }

    // decoder: dec1 1-term (q hi x Wd1 hi), dec2 1-term (d1 hi x Wd2 hi)
    wsplit_kernel<<<(256 * 768 + 255) / 256, 256>>>(Wd1, wth + 262144, wtm + 262144, 256, 768);
    mma_gemm<0, 1><<<dim3(6, 512), 256, SMEM_MMA>>>(256, 768, 1, h1h, h1h,
                                                    wth + 262144, wth + 262144, bd1,
                                                    nullptr, a0h, nullptr, nullptr, nullptr, nullptr);
    wsplit_kernel<<<(768 * 768 + 255) / 256, 256>>>(Wd2, wth + 458752, wtm + 458752, 768, 768);
    mma_gemm<2, 1><<<dim3(6, 512), 256, SMEM_MMA>>>(768, 768, 1, a0h, a0h,
                                                    wth + 458752, wth + 458752, bd2,
                                                    out + reconOff, nullptr, nullptr, x, accum, nullptr);

    if (fullOut) {
        finalize_kernel<<<1, 1>>>(accum, out);
    }
}